// round 1
// baseline (speedup 1.0000x reference)
#include <cuda_runtime.h>
#include <math.h>

#define BB   64
#define TT   1024
#define CC   512
#define HH   512
#define G4   2048
#define NCTA 128

// ---------------- scratch (static device memory; no allocs) ----------------
__device__ float g_xn[(size_t)TT * BB * CC];          // layernormed x, time-major [t*B+b][C]
__device__ float g_xg_f[(size_t)TT * BB * G4];        // input projection, fwd  [t*B+b][4H]
__device__ float g_xg_b[(size_t)TT * BB * G4];        // input projection, bwd
__device__ float g_hs_f[(size_t)TT * BB * HH];        // hidden states fwd [t][b][H]
__device__ float g_hs_b[(size_t)TT * BB * HH];        // hidden states bwd
__device__ float g_h[2][2][BB * HH];                  // [dir][parity][b*H] ping-pong h
__device__ float g_Hout[(size_t)BB * TT * HH];        // gated output, [b*T+t][H]
__device__ unsigned int g_bar;

__device__ __forceinline__ float sigf(float x) { return 1.f / (1.f + expf(-x)); }

// ---------------- block reduce ----------------
__device__ __forceinline__ float block_reduce(float v, float* red) {
    int lane = threadIdx.x & 31, wid = threadIdx.x >> 5;
#pragma unroll
    for (int o = 16; o > 0; o >>= 1) v += __shfl_xor_sync(0xffffffffu, v, o);
    if (lane == 0) red[wid] = v;
    __syncthreads();
    if (wid == 0) {
        float w = (lane < 8) ? red[lane] : 0.f;
#pragma unroll
        for (int o = 4; o > 0; o >>= 1) w += __shfl_xor_sync(0xffffffffu, w, o);
        if (lane == 0) red[8] = w;
    }
    __syncthreads();
    float r = red[8];
    __syncthreads();
    return r;
}

// ---------------- kernel 1: layernorm(x) -> g_xn (time-major) ----------------
__global__ void ln_x_kernel(const float* __restrict__ x,
                            const float* __restrict__ gx,
                            const float* __restrict__ bx) {
    __shared__ float red[9];
    int r = blockIdx.x;                 // r = b*T + t
    int b = r >> 10, t = r & 1023;
    const float* row = x + (size_t)r * CC;
    int c0 = threadIdx.x, c1 = threadIdx.x + 256;
    float v0 = row[c0], v1 = row[c1];
    float mean = block_reduce(v0 + v1, red) * (1.f / CC);
    float d0 = v0 - mean, d1 = v1 - mean;
    float var = block_reduce(d0 * d0 + d1 * d1, red) * (1.f / CC);
    float rstd = rsqrtf(var + 1e-5f);
    float* o = g_xn + ((size_t)t * BB + b) * CC;
    o[c0] = d0 * rstd * gx[c0] + bx[c0];
    o[c1] = d1 * rstd * gx[c1] + bx[c1];
}

// ---------------- kernel 2: input projection SGEMM ----------------
// Y[m][n] = sum_k xn[m][k] * Wih[n][k] + bih[n],  M=65536 N=2048 K=512, per dir
__global__ void __launch_bounds__(256, 2) proj_gemm_kernel(
    const float* __restrict__ Wf, const float* __restrict__ bf,
    const float* __restrict__ Wb, const float* __restrict__ bb_) {
    const int dir = blockIdx.z;
    const float* W    = dir ? Wb  : Wf;
    const float* bias = dir ? bb_ : bf;
    float* Y = dir ? g_xg_b : g_xg_f;
    const int m0 = blockIdx.y * 128;
    const int n0 = blockIdx.x * 128;
    __shared__ float As[8][128];
    __shared__ float Bs[8][128];
    const int tid = threadIdx.x;
    const int tx = tid & 15, ty = tid >> 4;
    const int lr = tid >> 1, lk = (tid & 1) * 4;
    float acc[8][8] = {{0.f}};

    const float* Aptr = g_xn + (size_t)(m0 + lr) * CC + lk;
    const float* Bptr = W + (size_t)(n0 + lr) * CC + lk;
    for (int k0 = 0; k0 < CC; k0 += 8) {
        float4 av = *(const float4*)(Aptr + k0);
        float4 bv = *(const float4*)(Bptr + k0);
        As[lk + 0][lr] = av.x; As[lk + 1][lr] = av.y; As[lk + 2][lr] = av.z; As[lk + 3][lr] = av.w;
        Bs[lk + 0][lr] = bv.x; Bs[lk + 1][lr] = bv.y; Bs[lk + 2][lr] = bv.z; Bs[lk + 3][lr] = bv.w;
        __syncthreads();
#pragma unroll
        for (int k = 0; k < 8; ++k) {
            float a[8], bq[8];
            *(float4*)&a[0]  = *(const float4*)&As[k][ty * 8];
            *(float4*)&a[4]  = *(const float4*)&As[k][ty * 8 + 4];
            *(float4*)&bq[0] = *(const float4*)&Bs[k][tx * 8];
            *(float4*)&bq[4] = *(const float4*)&Bs[k][tx * 8 + 4];
#pragma unroll
            for (int i = 0; i < 8; ++i)
#pragma unroll
                for (int j = 0; j < 8; ++j) acc[i][j] += a[i] * bq[j];
        }
        __syncthreads();
    }
    float bias8[8];
#pragma unroll
    for (int j = 0; j < 8; ++j) bias8[j] = bias[n0 + tx * 8 + j];
#pragma unroll
    for (int i = 0; i < 8; ++i) {
        float* orow = Y + (size_t)(m0 + ty * 8 + i) * G4 + n0 + tx * 8;
#pragma unroll
        for (int j = 0; j < 8; ++j) orow[j] = acc[i][j] + bias8[j];
    }
}

// ---------------- kernel 3a: barrier reset ----------------
__global__ void reset_kernel() { g_bar = 0u; }

// ---------------- kernel 3b: persistent bidirectional LSTM scan ----------------
// 128 CTAs: dir = bx>>6, hidden-unit slice j0 = (bx&63)*8 (8 units -> 32 gate cols)
__global__ void __launch_bounds__(256, 1) scan_kernel(
    const float* __restrict__ Whh_f, const float* __restrict__ bhh_f,
    const float* __restrict__ Whh_b, const float* __restrict__ bhh_b) {
    extern __shared__ float sm[];
    float* sW   = sm;              // [512][32] transposed Whh slice (64KB)
    float* sH   = sW + 512 * 32;   // [64][64] h k-chunk stage (16KB)
    float* sG   = sH + 64 * 64;    // [64][32] gates (8KB)
    float* sC   = sG + 64 * 32;    // [64*8] cell state (2KB)
    float* sBhh = sC + 512;        // [32]

    const int tid = threadIdx.x;
    const int dir = blockIdx.x >> 6;
    const int j0  = (blockIdx.x & 63) * 8;
    const float* Whh = dir ? Whh_b : Whh_f;
    const float* bhh = dir ? bhh_b : bhh_f;
    const float* xg  = dir ? g_xg_b : g_xg_f;
    float* hs        = dir ? g_hs_b : g_hs_f;

    // load Whh slice transposed: sW[k*32 + c], c = q*8+u -> row n = q*512 + j0 + u
    for (int idx = tid; idx < 512 * 32; idx += 256) {
        int c = idx & 31, k = idx >> 5;
        int n = (c >> 3) * 512 + j0 + (c & 7);
        sW[k * 32 + c] = Whh[(size_t)n * 512 + k];
    }
    if (tid < 32) {
        int n = (tid >> 3) * 512 + j0 + (tid & 7);
        sBhh[tid] = bhh[n];
    }
    // init cell state + h parity buffer 0
    for (int idx = tid; idx < 512; idx += 256) {
        sC[idx] = 0.f;
        int b = idx >> 3, u = idx & 7;
        __stcg(&g_h[dir][0][b * 512 + j0 + u], 0.f);
    }
    __threadfence();
    __syncthreads();
    if (tid == 0) {
        atomicAdd(&g_bar, 1u);
        while (*(volatile unsigned int*)&g_bar < (unsigned)NCTA) {}
    }
    __syncthreads();

    const int cx = tid & 7;          // col group: gate cols 4cx..4cx+3
    const int by = tid >> 3;         // batches 2by, 2by+1
    const int q  = cx >> 1;          // gate type of this col group
    const int ub = (cx & 1) * 4;     // unit offset within slice
    const int b0 = 2 * by, b1 = 2 * by + 1;

    for (int s = 0; s < TT; ++s) {
        const int t = dir ? (TT - 1 - s) : s;
        const float* hin = g_h[dir][s & 1];
        float* hout      = g_h[dir][(s + 1) & 1];

        // prefetch xg contributions (float4 over 4 consecutive units, same gate)
        size_t xoff = (size_t)t * BB * G4 + (size_t)q * 512 + j0 + ub;
        float4 xv0 = *(const float4*)(xg + xoff + (size_t)b0 * G4);
        float4 xv1 = *(const float4*)(xg + xoff + (size_t)b1 * G4);

        float acc0[4] = {0.f, 0.f, 0.f, 0.f};
        float acc1[4] = {0.f, 0.f, 0.f, 0.f};
        for (int kc = 0; kc < 512; kc += 64) {
#pragma unroll
            for (int rr = 0; rr < 4; ++rr) {
                int idx = tid + rr * 256;
                int bb2 = idx >> 4, kq = (idx & 15) << 2;
                float4 v = __ldcg((const float4*)(hin + bb2 * 512 + kc + kq));
                *(float4*)&sH[bb2 * 64 + kq] = v;
            }
            __syncthreads();
#pragma unroll 16
            for (int kk = 0; kk < 64; ++kk) {
                float4 w = *(const float4*)&sW[(kc + kk) * 32 + cx * 4];
                float h0 = sH[b0 * 64 + kk];
                float h1 = sH[b1 * 64 + kk];
                acc0[0] += h0 * w.x; acc0[1] += h0 * w.y; acc0[2] += h0 * w.z; acc0[3] += h0 * w.w;
                acc1[0] += h1 * w.x; acc1[1] += h1 * w.y; acc1[2] += h1 * w.z; acc1[3] += h1 * w.w;
            }
            __syncthreads();
        }
        float4 bb4 = *(const float4*)&sBhh[cx * 4];
        *(float4*)&sG[b0 * 32 + cx * 4] =
            make_float4(acc0[0] + bb4.x + xv0.x, acc0[1] + bb4.y + xv0.y,
                        acc0[2] + bb4.z + xv0.z, acc0[3] + bb4.w + xv0.w);
        *(float4*)&sG[b1 * 32 + cx * 4] =
            make_float4(acc1[0] + bb4.x + xv1.x, acc1[1] + bb4.y + xv1.y,
                        acc1[2] + bb4.z + xv1.z, acc1[3] + bb4.w + xv1.w);
        __syncthreads();
        // cell/hidden update: idx = b*8 + u over 512 states
#pragma unroll
        for (int rr = 0; rr < 2; ++rr) {
            int idx = tid + rr * 256;
            int b = idx >> 3, u = idx & 7;
            float gi = sG[b * 32 + u];
            float gf = sG[b * 32 + 8 + u];
            float gg = sG[b * 32 + 16 + u];
            float go = sG[b * 32 + 24 + u];
            float cnew = sigf(gf) * sC[idx] + sigf(gi) * tanhf(gg);
            float hnew = sigf(go) * tanhf(cnew);
            sC[idx] = cnew;
            __stcg(&hout[b * 512 + j0 + u], hnew);
            hs[((size_t)t * BB + b) * 512 + j0 + u] = hnew;
        }
        __threadfence();
        __syncthreads();
        if (tid == 0) {
            unsigned tg2 = (unsigned)(s + 2) * NCTA;
            atomicAdd(&g_bar, 1u);
            while (*(volatile unsigned int*)&g_bar < tg2) {}
        }
        __syncthreads();
    }
}

// ---------------- kernel 4: gate fusion GEMM + combine ----------------
// sigma[m][n] = sigmoid(cat(fw,bw)[m] . Wg[n] + bg[n]); Hout = s*fw + (1-s)*bw
// m = b*T + t, M=65536 N=512 K=1024
__global__ void __launch_bounds__(256, 2) gate_gemm_kernel(
    const float* __restrict__ Wg, const float* __restrict__ bg) {
    const int m0 = blockIdx.y * 128;
    const int n0 = blockIdx.x * 128;
    __shared__ float As[8][128];
    __shared__ float Bs[8][128];
    const int tid = threadIdx.x;
    const int tx = tid & 15, ty = tid >> 4;
    const int lr = tid >> 1, lk = (tid & 1) * 4;
    float acc[8][8] = {{0.f}};

    const int am = m0 + lr;
    const int ab = am >> 10, at = am & 1023;
    const float* Arow0 = g_hs_f + ((size_t)at * BB + ab) * HH;
    const float* Arow1 = g_hs_b + ((size_t)at * BB + ab) * HH;
    const float* Brow  = Wg + (size_t)(n0 + lr) * 1024 + lk;

    for (int k0 = 0; k0 < 1024; k0 += 8) {
        const float* ap = (k0 < 512) ? (Arow0 + k0 + lk) : (Arow1 + (k0 - 512) + lk);
        float4 av = *(const float4*)ap;
        float4 bv = *(const float4*)(Brow + k0);
        As[lk + 0][lr] = av.x; As[lk + 1][lr] = av.y; As[lk + 2][lr] = av.z; As[lk + 3][lr] = av.w;
        Bs[lk + 0][lr] = bv.x; Bs[lk + 1][lr] = bv.y; Bs[lk + 2][lr] = bv.z; Bs[lk + 3][lr] = bv.w;
        __syncthreads();
#pragma unroll
        for (int k = 0; k < 8; ++k) {
            float a[8], bq[8];
            *(float4*)&a[0]  = *(const float4*)&As[k][ty * 8];
            *(float4*)&a[4]  = *(const float4*)&As[k][ty * 8 + 4];
            *(float4*)&bq[0] = *(const float4*)&Bs[k][tx * 8];
            *(float4*)&bq[4] = *(const float4*)&Bs[k][tx * 8 + 4];
#pragma unroll
            for (int i = 0; i < 8; ++i)
#pragma unroll
                for (int j = 0; j < 8; ++j) acc[i][j] += a[i] * bq[j];
        }
        __syncthreads();
    }
    float bg8[8];
#pragma unroll
    for (int j = 0; j < 8; ++j) bg8[j] = bg[n0 + tx * 8 + j];
#pragma unroll
    for (int i = 0; i < 8; ++i) {
        int m = m0 + ty * 8 + i;
        int b = m >> 10, t = m & 1023;
        const float* fwr = g_hs_f + ((size_t)t * BB + b) * HH + n0 + tx * 8;
        const float* bwr = g_hs_b + ((size_t)t * BB + b) * HH + n0 + tx * 8;
        float* orow = g_Hout + (size_t)m * HH + n0 + tx * 8;
#pragma unroll
        for (int j = 0; j < 8; ++j) {
            float sgm = sigf(acc[i][j] + bg8[j]);
            orow[j] = sgm * fwr[j] + (1.f - sgm) * bwr[j];
        }
    }
}

// ---------------- kernel 5: final layernorm -> d_out ----------------
__global__ void ln_out_kernel(const float* __restrict__ gH,
                              const float* __restrict__ bH,
                              float* __restrict__ out) {
    __shared__ float red[9];
    int r = blockIdx.x;                 // r = b*T + t
    const float* row = g_Hout + (size_t)r * HH;
    int c0 = threadIdx.x, c1 = threadIdx.x + 256;
    float v0 = row[c0], v1 = row[c1];
    float mean = block_reduce(v0 + v1, red) * (1.f / HH);
    float d0 = v0 - mean, d1 = v1 - mean;
    float var = block_reduce(d0 * d0 + d1 * d1, red) * (1.f / HH);
    float rstd = rsqrtf(var + 1e-5f);
    out[(size_t)r * HH + c0] = d0 * rstd * gH[c0] + bH[c0];
    out[(size_t)r * HH + c1] = d1 * rstd * gH[c1] + bH[c1];
}

// ---------------- launch ----------------
extern "C" void kernel_launch(void* const* d_in, const int* in_sizes, int n_in,
                              void* d_out, int out_size) {
    const float* x     = (const float*)d_in[0];
    // d_in[1] = ts (unused by forward)
    const float* Wih_f = (const float*)d_in[2];
    const float* Whh_f = (const float*)d_in[3];
    const float* bih_f = (const float*)d_in[4];
    const float* bhh_f = (const float*)d_in[5];
    const float* Wih_b = (const float*)d_in[6];
    const float* Whh_b = (const float*)d_in[7];
    const float* bih_b = (const float*)d_in[8];
    const float* bhh_b = (const float*)d_in[9];
    const float* Wg    = (const float*)d_in[10];
    const float* bg    = (const float*)d_in[11];
    const float* gx    = (const float*)d_in[12];
    const float* bx    = (const float*)d_in[13];
    const float* gH    = (const float*)d_in[14];
    const float* bH    = (const float*)d_in[15];
    float* out = (float*)d_out;

    const int scan_smem = (512 * 32 + 64 * 64 + 64 * 32 + 512 + 32) * (int)sizeof(float);
    cudaFuncSetAttribute(scan_kernel, cudaFuncAttributeMaxDynamicSharedMemorySize, scan_smem);

    ln_x_kernel<<<BB * TT, 256>>>(x, gx, bx);
    proj_gemm_kernel<<<dim3(G4 / 128, (BB * TT) / 128, 2), 256>>>(Wih_f, bih_f, Wih_b, bih_b);
    reset_kernel<<<1, 1>>>();
    scan_kernel<<<NCTA, 256, scan_smem>>>(Whh_f, bhh_f, Whh_b, bhh_b);
    gate_gemm_kernel<<<dim3(HH / 128, (BB * TT) / 128), 256>>>(Wg, bg);
    ln_out_kernel<<<BB * TT, 256>>>(gH, bH, out);
}

// round 3
// speedup vs baseline: 1.2725x; 1.2725x over previous
#include <cuda_runtime.h>
#include <cuda_bf16.h>
#include <math.h>

#define BB   64
#define TT   1024
#define CC   512
#define HH   512
#define G4   2048
#define NCTA 128
#define PADK 40   // padded k-stride (elements) for GEMM smem tiles

// ---------------- scratch (static device memory; no allocs) ----------------
__device__ __nv_bfloat16 g_Axn_hi[(size_t)TT * BB * CC];   // LN(x) bf16 hi, time-major [t*B+b][C]
__device__ __nv_bfloat16 g_Axn_lo[(size_t)TT * BB * CC];
__device__ __nv_bfloat16 g_Bp_hi[4096 * 512];              // stacked Wih_f | Wih_b
__device__ __nv_bfloat16 g_Bp_lo[4096 * 512];
__device__ float g_xg_f[(size_t)TT * BB * G4];             // input projection fwd [t*B+b][4H]
__device__ float g_xg_b[(size_t)TT * BB * G4];
__device__ float g_hs_f[(size_t)BB * TT * HH];             // hidden fp32 [b*T+t][H]
__device__ float g_hs_b[(size_t)BB * TT * HH];
__device__ __nv_bfloat16 g_Acat_hi[(size_t)BB * TT * 2 * HH]; // concat(fw,bw) [b*T+t][2H]
__device__ __nv_bfloat16 g_Acat_lo[(size_t)BB * TT * 2 * HH];
__device__ __nv_bfloat16 g_Bg_hi[512 * 1024];
__device__ __nv_bfloat16 g_Bg_lo[512 * 1024];
__device__ float g_h[2][2][BB * HH];                       // ping-pong h
__device__ float g_Hout[(size_t)BB * TT * HH];
__device__ unsigned int g_bar;

__device__ __forceinline__ float sigf(float x) { return 1.f / (1.f + expf(-x)); }

// ---------------- f32x2 packed FMA helpers ----------------
__device__ __forceinline__ unsigned long long pk2(float x) {
    unsigned long long r;
    asm("mov.b64 %0, {%1, %1};" : "=l"(r) : "f"(x));
    return r;
}
__device__ __forceinline__ void f2ma(unsigned long long& d, unsigned long long a, unsigned long long b) {
    asm("fma.rn.f32x2 %0, %1, %2, %0;" : "+l"(d) : "l"(a), "l"(b));
}
__device__ __forceinline__ float2 up2(unsigned long long v) {
    float2 r;
    asm("mov.b64 {%0, %1}, %2;" : "=f"(r.x), "=f"(r.y) : "l"(v));
    return r;
}

// ---------------- mma.sync bf16 helper ----------------
__device__ __forceinline__ void mma_bf16(float* d, const unsigned* a, const unsigned* b) {
    asm volatile(
        "mma.sync.aligned.m16n8k16.row.col.f32.bf16.bf16.f32 "
        "{%0,%1,%2,%3}, {%4,%5,%6,%7}, {%8,%9}, {%0,%1,%2,%3};"
        : "+f"(d[0]), "+f"(d[1]), "+f"(d[2]), "+f"(d[3])
        : "r"(a[0]), "r"(a[1]), "r"(a[2]), "r"(a[3]), "r"(b[0]), "r"(b[1]));
}

// ---------------- block reduce ----------------
__device__ __forceinline__ float block_reduce(float v, float* red) {
    int lane = threadIdx.x & 31, wid = threadIdx.x >> 5;
#pragma unroll
    for (int o = 16; o > 0; o >>= 1) v += __shfl_xor_sync(0xffffffffu, v, o);
    if (lane == 0) red[wid] = v;
    __syncthreads();
    if (wid == 0) {
        float w = (lane < 8) ? red[lane] : 0.f;
#pragma unroll
        for (int o = 4; o > 0; o >>= 1) w += __shfl_xor_sync(0xffffffffu, w, o);
        if (lane == 0) red[8] = w;
    }
    __syncthreads();
    float r = red[8];
    __syncthreads();
    return r;
}

// ---------------- kernel 1: layernorm(x) -> bf16 hi/lo (time-major) ----------------
__global__ void ln_x_kernel(const float* __restrict__ x,
                            const float* __restrict__ gx,
                            const float* __restrict__ bx) {
    __shared__ float red[9];
    int r = blockIdx.x;                 // r = b*T + t
    int b = r >> 10, t = r & 1023;
    const float* row = x + (size_t)r * CC;
    int c0 = threadIdx.x, c1 = threadIdx.x + 256;
    float v0 = row[c0], v1 = row[c1];
    float mean = block_reduce(v0 + v1, red) * (1.f / CC);
    float d0 = v0 - mean, d1 = v1 - mean;
    float var = block_reduce(d0 * d0 + d1 * d1, red) * (1.f / CC);
    float rstd = rsqrtf(var + 1e-5f);
    size_t base = ((size_t)t * BB + b) * CC;
    float y0 = d0 * rstd * gx[c0] + bx[c0];
    float y1 = d1 * rstd * gx[c1] + bx[c1];
    __nv_bfloat16 h0 = __float2bfloat16(y0);
    __nv_bfloat16 h1 = __float2bfloat16(y1);
    g_Axn_hi[base + c0] = h0;
    g_Axn_hi[base + c1] = h1;
    g_Axn_lo[base + c0] = __float2bfloat16(y0 - __bfloat162float(h0));
    g_Axn_lo[base + c1] = __float2bfloat16(y1 - __bfloat162float(h1));
}

// ---------------- weight conversion kernels ----------------
__global__ void convW_proj(const float* __restrict__ Wf, const float* __restrict__ Wb) {
    int n = blockIdx.x;  // 0..4095
    const float* src = (n < 2048) ? (Wf + (size_t)n * 512) : (Wb + (size_t)(n - 2048) * 512);
    size_t base = (size_t)n * 512;
    for (int k = threadIdx.x; k < 512; k += 256) {
        float v = src[k];
        __nv_bfloat16 h = __float2bfloat16(v);
        g_Bp_hi[base + k] = h;
        g_Bp_lo[base + k] = __float2bfloat16(v - __bfloat162float(h));
    }
}

__global__ void convW_gate(const float* __restrict__ Wg) {
    int n = blockIdx.x;  // 0..511
    size_t base = (size_t)n * 1024;
    for (int k = threadIdx.x; k < 1024; k += 256) {
        float v = Wg[base + k];
        __nv_bfloat16 h = __float2bfloat16(v);
        g_Bg_hi[base + k] = h;
        g_Bg_lo[base + k] = __float2bfloat16(v - __bfloat162float(h));
    }
}

// ---------------- HMMA GEMM: D[M,N] = A[M,K] . B[N,K]^T (bf16 hi/lo, 3 passes) ----------
// 128x128 CTA tile, 256 threads = 8 warps (warp tile 32x64). BK=32 chunks,
// register prefetch over single smem stage.
// EPI 0: proj epilogue (bias -> g_xg_f/g_xg_b fp32)
// EPI 1: gate epilogue (sigmoid blend fw/bw -> g_Hout)
template <int KDIM, int EPI>
__global__ void __launch_bounds__(256, 1) mm_kernel(const float* __restrict__ bias0,
                                                    const float* __restrict__ bias1) {
    __shared__ __nv_bfloat16 sAh[128 * PADK];
    __shared__ __nv_bfloat16 sAl[128 * PADK];
    __shared__ __nv_bfloat16 sBh[128 * PADK];
    __shared__ __nv_bfloat16 sBl[128 * PADK];

    const int tid = threadIdx.x;
    const int warp = tid >> 5, lane = tid & 31;
    const int g = lane >> 2, q = lane & 3;
    const int wm = (warp >> 1) * 32;
    const int wn = (warp & 1) * 64;
    const int m0 = blockIdx.y * 128;
    const int n0 = blockIdx.x * 128;

    const __nv_bfloat16* Ahi = (EPI == 0) ? g_Axn_hi : g_Acat_hi;
    const __nv_bfloat16* Alo = (EPI == 0) ? g_Axn_lo : g_Acat_lo;
    const __nv_bfloat16* Bhi = (EPI == 0) ? g_Bp_hi : g_Bg_hi;
    const __nv_bfloat16* Blo = (EPI == 0) ? g_Bp_lo : g_Bg_lo;

    // per-thread load slots: chunk rows/cols
    const int r0 = tid >> 2, kq0 = (tid & 3) * 8;          // slot 0
    const int r1 = (tid + 256) >> 2, kq1 = ((tid + 256) & 3) * 8; // slot 1
    const __nv_bfloat16* pAh0 = Ahi + (size_t)(m0 + r0) * KDIM + kq0;
    const __nv_bfloat16* pAh1 = Ahi + (size_t)(m0 + r1) * KDIM + kq1;
    const __nv_bfloat16* pAl0 = Alo + (size_t)(m0 + r0) * KDIM + kq0;
    const __nv_bfloat16* pAl1 = Alo + (size_t)(m0 + r1) * KDIM + kq1;
    const __nv_bfloat16* pBh0 = Bhi + (size_t)(n0 + r0) * KDIM + kq0;
    const __nv_bfloat16* pBh1 = Bhi + (size_t)(n0 + r1) * KDIM + kq1;
    const __nv_bfloat16* pBl0 = Blo + (size_t)(n0 + r0) * KDIM + kq0;
    const __nv_bfloat16* pBl1 = Blo + (size_t)(n0 + r1) * KDIM + kq1;

    float acc[2][8][4];
#pragma unroll
    for (int i = 0; i < 2; ++i)
#pragma unroll
        for (int j = 0; j < 8; ++j)
#pragma unroll
            for (int v = 0; v < 4; ++v) acc[i][j][v] = 0.f;

    // prologue: load chunk 0
    uint4 vAh0 = *(const uint4*)pAh0, vAh1 = *(const uint4*)pAh1;
    uint4 vAl0 = *(const uint4*)pAl0, vAl1 = *(const uint4*)pAl1;
    uint4 vBh0 = *(const uint4*)pBh0, vBh1 = *(const uint4*)pBh1;
    uint4 vBl0 = *(const uint4*)pBl0, vBl1 = *(const uint4*)pBl1;

    const int NCH = KDIM / 32;
    for (int c = 0; c < NCH; ++c) {
        // store prefetched chunk to smem
        *(uint4*)&sAh[r0 * PADK + kq0] = vAh0;  *(uint4*)&sAh[r1 * PADK + kq1] = vAh1;
        *(uint4*)&sAl[r0 * PADK + kq0] = vAl0;  *(uint4*)&sAl[r1 * PADK + kq1] = vAl1;
        *(uint4*)&sBh[r0 * PADK + kq0] = vBh0;  *(uint4*)&sBh[r1 * PADK + kq1] = vBh1;
        *(uint4*)&sBl[r0 * PADK + kq0] = vBl0;  *(uint4*)&sBl[r1 * PADK + kq1] = vBl1;
        __syncthreads();

        // issue prefetch of next chunk
        if (c + 1 < NCH) {
            int koff = (c + 1) * 32;
            vAh0 = *(const uint4*)(pAh0 + koff);  vAh1 = *(const uint4*)(pAh1 + koff);
            vAl0 = *(const uint4*)(pAl0 + koff);  vAl1 = *(const uint4*)(pAl1 + koff);
            vBh0 = *(const uint4*)(pBh0 + koff);  vBh1 = *(const uint4*)(pBh1 + koff);
            vBl0 = *(const uint4*)(pBl0 + koff);  vBl1 = *(const uint4*)(pBl1 + koff);
        }

        // compute: 2 k16 steps
#pragma unroll
        for (int ks = 0; ks < 32; ks += 16) {
            unsigned ah[2][4], al[2][4];
#pragma unroll
            for (int mt = 0; mt < 2; ++mt) {
                int row = wm + mt * 16 + g;
                const unsigned* ph0 = (const unsigned*)&sAh[row * PADK + ks];
                const unsigned* ph1 = (const unsigned*)&sAh[(row + 8) * PADK + ks];
                ah[mt][0] = ph0[q]; ah[mt][1] = ph1[q]; ah[mt][2] = ph0[q + 4]; ah[mt][3] = ph1[q + 4];
                const unsigned* pl0 = (const unsigned*)&sAl[row * PADK + ks];
                const unsigned* pl1 = (const unsigned*)&sAl[(row + 8) * PADK + ks];
                al[mt][0] = pl0[q]; al[mt][1] = pl1[q]; al[mt][2] = pl0[q + 4]; al[mt][3] = pl1[q + 4];
            }
#pragma unroll
            for (int nt = 0; nt < 8; ++nt) {
                int nrow = wn + nt * 8 + g;
                const unsigned* pb = (const unsigned*)&sBh[nrow * PADK + ks];
                unsigned bh[2] = {pb[q], pb[q + 4]};
                const unsigned* pbl = (const unsigned*)&sBl[nrow * PADK + ks];
                unsigned bl[2] = {pbl[q], pbl[q + 4]};
#pragma unroll
                for (int mt = 0; mt < 2; ++mt) {
                    mma_bf16(acc[mt][nt], ah[mt], bh);
                    mma_bf16(acc[mt][nt], ah[mt], bl);
                    mma_bf16(acc[mt][nt], al[mt], bh);
                }
            }
        }
        __syncthreads();
    }

    // ---------------- epilogue ----------------
    if (EPI == 0) {
        const bool isf = (n0 < 2048);
        float* Y = isf ? g_xg_f : g_xg_b;
        const float* bias = isf ? bias0 : bias1;
        const int nb = (n0 & 2047) + wn;
#pragma unroll
        for (int mt = 0; mt < 2; ++mt) {
            int mrow = m0 + wm + mt * 16 + g;
#pragma unroll
            for (int nt = 0; nt < 8; ++nt) {
                int ncol = nb + nt * 8 + 2 * q;
                float bx0 = bias[ncol], bx1 = bias[ncol + 1];
                float2 v0 = make_float2(acc[mt][nt][0] + bx0, acc[mt][nt][1] + bx1);
                float2 v1 = make_float2(acc[mt][nt][2] + bx0, acc[mt][nt][3] + bx1);
                *(float2*)(Y + (size_t)mrow * 2048 + ncol) = v0;
                *(float2*)(Y + (size_t)(mrow + 8) * 2048 + ncol) = v1;
            }
        }
    } else {
#pragma unroll
        for (int mt = 0; mt < 2; ++mt) {
            int mrow = m0 + wm + mt * 16 + g;
#pragma unroll
            for (int nt = 0; nt < 8; ++nt) {
                int ncol = n0 + wn + nt * 8 + 2 * q;
                float bx0 = bias0[ncol], bx1 = bias0[ncol + 1];
#pragma unroll
                for (int hh = 0; hh < 2; ++hh) {
                    int m = mrow + hh * 8;
                    float s0 = sigf(acc[mt][nt][2 * hh + 0] + bx0);
                    float s1 = sigf(acc[mt][nt][2 * hh + 1] + bx1);
                    float2 fw = *(const float2*)(g_hs_f + (size_t)m * 512 + ncol);
                    float2 bw = *(const float2*)(g_hs_b + (size_t)m * 512 + ncol);
                    float2 o;
                    o.x = s0 * fw.x + (1.f - s0) * bw.x;
                    o.y = s1 * fw.y + (1.f - s1) * bw.y;
                    *(float2*)(g_Hout + (size_t)m * 512 + ncol) = o;
                }
            }
        }
    }
}

// ---------------- barrier reset ----------------
__global__ void reset_kernel() { g_bar = 0u; }

// ---------------- persistent bidirectional LSTM scan (f32x2 inner loop) -----------
__global__ void __launch_bounds__(256, 1) scan_kernel(
    const float* __restrict__ Whh_f, const float* __restrict__ bhh_f,
    const float* __restrict__ Whh_b, const float* __restrict__ bhh_b) {
    extern __shared__ float smf[];
    float* sW   = smf;             // [512][32] transposed Whh slice (64KB)
    float* sH   = sW + 512 * 32;   // [64][64] h k-chunk stage (16KB)
    float* sG   = sH + 64 * 64;    // [64][32] gates (8KB)
    float* sC   = sG + 64 * 32;    // [64*8] cell state (2KB)
    float* sBhh = sC + 512;        // [32]

    const int tid = threadIdx.x;
    const int dir = blockIdx.x >> 6;
    const int j0  = (blockIdx.x & 63) * 8;
    const float* Whh = dir ? Whh_b : Whh_f;
    const float* bhh = dir ? bhh_b : bhh_f;
    const float* xg  = dir ? g_xg_b : g_xg_f;
    float* hs        = dir ? g_hs_b : g_hs_f;

    for (int idx = tid; idx < 512 * 32; idx += 256) {
        int c = idx & 31, k = idx >> 5;
        int n = (c >> 3) * 512 + j0 + (c & 7);
        sW[k * 32 + c] = Whh[(size_t)n * 512 + k];
    }
    if (tid < 32) {
        int n = (tid >> 3) * 512 + j0 + (tid & 7);
        sBhh[tid] = bhh[n];
    }
    for (int idx = tid; idx < 512; idx += 256) {
        sC[idx] = 0.f;
        int b = idx >> 3, u = idx & 7;
        __stcg(&g_h[dir][0][b * 512 + j0 + u], 0.f);
    }
    __threadfence();
    __syncthreads();
    if (tid == 0) {
        atomicAdd(&g_bar, 1u);
        while (*(volatile unsigned int*)&g_bar < (unsigned)NCTA) {}
    }
    __syncthreads();

    const int cx = tid & 7;          // gate cols 4cx..4cx+3
    const int by = tid >> 3;
    const int q  = cx >> 1;
    const int ub = (cx & 1) * 4;
    const int b0 = 2 * by, b1 = 2 * by + 1;

    for (int s = 0; s < TT; ++s) {
        const int t = dir ? (TT - 1 - s) : s;
        const float* hin = g_h[dir][s & 1];
        float* hout      = g_h[dir][(s + 1) & 1];

        size_t xoff = (size_t)t * BB * G4 + (size_t)q * 512 + j0 + ub;
        float4 xv0 = *(const float4*)(xg + xoff + (size_t)b0 * G4);
        float4 xv1 = *(const float4*)(xg + xoff + (size_t)b1 * G4);

        unsigned long long a0p0 = pk2(0.f), a0p1 = pk2(0.f);
        unsigned long long a1p0 = pk2(0.f), a1p1 = pk2(0.f);

        for (int kc = 0; kc < 512; kc += 64) {
#pragma unroll
            for (int rr = 0; rr < 4; ++rr) {
                int idx = tid + rr * 256;
                int bb2 = idx >> 4, kq = (idx & 15) << 2;
                float4 v = __ldcg((const float4*)(hin + bb2 * 512 + kc + kq));
                *(float4*)&sH[bb2 * 64 + kq] = v;
            }
            __syncthreads();
#pragma unroll
            for (int kk = 0; kk < 64; kk += 2) {
                ulonglong2 w0 = *(const ulonglong2*)&sW[(kc + kk) * 32 + cx * 4];
                ulonglong2 w1 = *(const ulonglong2*)&sW[(kc + kk + 1) * 32 + cx * 4];
                float2 ha = *(const float2*)&sH[b0 * 64 + kk];
                float2 hb = *(const float2*)&sH[b1 * 64 + kk];
                unsigned long long p;
                p = pk2(ha.x); f2ma(a0p0, p, w0.x); f2ma(a0p1, p, w0.y);
                p = pk2(ha.y); f2ma(a0p0, p, w1.x); f2ma(a0p1, p, w1.y);
                p = pk2(hb.x); f2ma(a1p0, p, w0.x); f2ma(a1p1, p, w0.y);
                p = pk2(hb.y); f2ma(a1p0, p, w1.x); f2ma(a1p1, p, w1.y);
            }
            __syncthreads();
        }
        float2 a00 = up2(a0p0), a01 = up2(a0p1);
        float2 a10 = up2(a1p0), a11 = up2(a1p1);
        float4 bb4 = *(const float4*)&sBhh[cx * 4];
        *(float4*)&sG[b0 * 32 + cx * 4] =
            make_float4(a00.x + bb4.x + xv0.x, a00.y + bb4.y + xv0.y,
                        a01.x + bb4.z + xv0.z, a01.y + bb4.w + xv0.w);
        *(float4*)&sG[b1 * 32 + cx * 4] =
            make_float4(a10.x + bb4.x + xv1.x, a10.y + bb4.y + xv1.y,
                        a11.x + bb4.z + xv1.z, a11.y + bb4.w + xv1.w);
        __syncthreads();
#pragma unroll
        for (int rr = 0; rr < 2; ++rr) {
            int idx = tid + rr * 256;
            int b = idx >> 3, u = idx & 7;
            float gi = sG[b * 32 + u];
            float gf = sG[b * 32 + 8 + u];
            float gg = sG[b * 32 + 16 + u];
            float go = sG[b * 32 + 24 + u];
            float cnew = sigf(gf) * sC[idx] + sigf(gi) * tanhf(gg);
            float hnew = sigf(go) * tanhf(cnew);
            sC[idx] = cnew;
            __stcg(&hout[b * 512 + j0 + u], hnew);
            size_t mrow = (size_t)b * TT + t;
            hs[mrow * 512 + j0 + u] = hnew;
            __nv_bfloat16 hhi = __float2bfloat16(hnew);
            size_t ar = mrow * 1024 + (size_t)dir * 512 + j0 + u;
            g_Acat_hi[ar] = hhi;
            g_Acat_lo[ar] = __float2bfloat16(hnew - __bfloat162float(hhi));
        }
        __threadfence();
        __syncthreads();
        if (tid == 0) {
            unsigned tg2 = (unsigned)(s + 2) * NCTA;
            atomicAdd(&g_bar, 1u);
            while (*(volatile unsigned int*)&g_bar < tg2) {}
        }
        __syncthreads();
    }
}

// ---------------- final layernorm -> d_out ----------------
__global__ void ln_out_kernel(const float* __restrict__ gH,
                              const float* __restrict__ bH,
                              float* __restrict__ out) {
    __shared__ float red[9];
    int r = blockIdx.x;                 // r = b*T + t
    const float* row = g_Hout + (size_t)r * HH;
    int c0 = threadIdx.x, c1 = threadIdx.x + 256;
    float v0 = row[c0], v1 = row[c1];
    float mean = block_reduce(v0 + v1, red) * (1.f / HH);
    float d0 = v0 - mean, d1 = v1 - mean;
    float var = block_reduce(d0 * d0 + d1 * d1, red) * (1.f / HH);
    float rstd = rsqrtf(var + 1e-5f);
    out[(size_t)r * HH + c0] = d0 * rstd * gH[c0] + bH[c0];
    out[(size_t)r * HH + c1] = d1 * rstd * gH[c1] + bH[c1];
}

// ---------------- launch ----------------
extern "C" void kernel_launch(void* const* d_in, const int* in_sizes, int n_in,
                              void* d_out, int out_size) {
    const float* x     = (const float*)d_in[0];
    const float* Wih_f = (const float*)d_in[2];
    const float* Whh_f = (const float*)d_in[3];
    const float* bih_f = (const float*)d_in[4];
    const float* bhh_f = (const float*)d_in[5];
    const float* Wih_b = (const float*)d_in[6];
    const float* Whh_b = (const float*)d_in[7];
    const float* bih_b = (const float*)d_in[8];
    const float* bhh_b = (const float*)d_in[9];
    const float* Wg    = (const float*)d_in[10];
    const float* bg    = (const float*)d_in[11];
    const float* gx    = (const float*)d_in[12];
    const float* bx    = (const float*)d_in[13];
    const float* gH    = (const float*)d_in[14];
    const float* bH    = (const float*)d_in[15];
    float* out = (float*)d_out;

    const int scan_smem = (512 * 32 + 64 * 64 + 64 * 32 + 512 + 32) * (int)sizeof(float);
    cudaFuncSetAttribute(scan_kernel, cudaFuncAttributeMaxDynamicSharedMemorySize, scan_smem);

    ln_x_kernel<<<BB * TT, 256>>>(x, gx, bx);
    convW_proj<<<4096, 256>>>(Wih_f, Wih_b);
    convW_gate<<<512, 256>>>(Wg);
    mm_kernel<512, 0><<<dim3(4096 / 128, (BB * TT) / 128), 256>>>(bih_f, bih_b);
    reset_kernel<<<1, 1>>>();
    scan_kernel<<<NCTA, 256, scan_smem>>>(Whh_f, bhh_f, Whh_b, bhh_b);
    mm_kernel<1024, 1><<<dim3(512 / 128, (BB * TT) / 128), 256>>>(bg, bg);
    ln_out_kernel<<<BB * TT, 256>>>(gH, bH, out);
}

// round 4
// speedup vs baseline: 2.3449x; 1.8428x over previous
#include <cuda_runtime.h>
#include <cuda_bf16.h>
#include <math.h>

#define BB   64
#define TT   1024
#define CC   512
#define HH   512
#define G4   2048
#define PADK 40   // padded k-stride for mm_kernel smem tiles
#define SPAD 520  // padded k-stride (elements) for scan smem tiles

// ---------------- scratch (static device memory; no allocs) ----------------
__device__ __nv_bfloat16 g_Axn_hi[(size_t)TT * BB * CC];   // LN(x) bf16 hi, time-major [t*B+b][C]
__device__ __nv_bfloat16 g_Axn_lo[(size_t)TT * BB * CC];
__device__ __nv_bfloat16 g_Bp_hi[4096 * 512];              // stacked Wih_f | Wih_b
__device__ __nv_bfloat16 g_Bp_lo[4096 * 512];
__device__ float g_xg_f[(size_t)TT * BB * G4];             // input projection fwd [t*B+b][4H]
__device__ float g_xg_b[(size_t)TT * BB * G4];
__device__ float g_hs_f[(size_t)BB * TT * HH];             // hidden fp32 [b*T+t][H]
__device__ float g_hs_b[(size_t)BB * TT * HH];
__device__ __nv_bfloat16 g_Acat_hi[(size_t)BB * TT * 2 * HH]; // concat(fw,bw) [b*T+t][2H]
__device__ __nv_bfloat16 g_Acat_lo[(size_t)BB * TT * 2 * HH];
__device__ __nv_bfloat16 g_Bg_hi[512 * 1024];
__device__ __nv_bfloat16 g_Bg_lo[512 * 1024];
__device__ __nv_bfloat16 g_hx_hi[2][2][BB * HH];           // [dir][parity] bf16 h exchange
__device__ __nv_bfloat16 g_hx_lo[2][2][BB * HH];
__device__ float g_Hout[(size_t)BB * TT * HH];
__device__ unsigned int g_barr[64];                        // per-dir counters at [0], [32]

__device__ __forceinline__ float sigf(float x) { return 1.f / (1.f + expf(-x)); }

// ---------------- mma.sync bf16 helper ----------------
__device__ __forceinline__ void mma_bf16(float* d, const unsigned* a, const unsigned* b) {
    asm volatile(
        "mma.sync.aligned.m16n8k16.row.col.f32.bf16.bf16.f32 "
        "{%0,%1,%2,%3}, {%4,%5,%6,%7}, {%8,%9}, {%0,%1,%2,%3};"
        : "+f"(d[0]), "+f"(d[1]), "+f"(d[2]), "+f"(d[3])
        : "r"(a[0]), "r"(a[1]), "r"(a[2]), "r"(a[3]), "r"(b[0]), "r"(b[1]));
}

#define LDSMX4(R, ADDR) \
    asm volatile("ldmatrix.sync.aligned.m8n8.x4.shared.b16 {%0,%1,%2,%3}, [%4];" \
                 : "=r"((R)[0]), "=r"((R)[1]), "=r"((R)[2]), "=r"((R)[3]) : "r"(ADDR))

#define CPASYNC16(SMEM, GPTR) \
    asm volatile("cp.async.cg.shared.global [%0], [%1], 16;" :: "r"(SMEM), "l"(GPTR))
#define CPASYNC_WAIT() \
    do { asm volatile("cp.async.commit_group;"); \
         asm volatile("cp.async.wait_group 0;" ::: "memory"); } while (0)

// ---------------- block reduce ----------------
__device__ __forceinline__ float block_reduce(float v, float* red) {
    int lane = threadIdx.x & 31, wid = threadIdx.x >> 5;
#pragma unroll
    for (int o = 16; o > 0; o >>= 1) v += __shfl_xor_sync(0xffffffffu, v, o);
    if (lane == 0) red[wid] = v;
    __syncthreads();
    if (wid == 0) {
        float w = (lane < 8) ? red[lane] : 0.f;
#pragma unroll
        for (int o = 4; o > 0; o >>= 1) w += __shfl_xor_sync(0xffffffffu, w, o);
        if (lane == 0) red[8] = w;
    }
    __syncthreads();
    float r = red[8];
    __syncthreads();
    return r;
}

// ---------------- kernel 1: layernorm(x) -> bf16 hi/lo (time-major) ----------------
__global__ void ln_x_kernel(const float* __restrict__ x,
                            const float* __restrict__ gx,
                            const float* __restrict__ bx) {
    __shared__ float red[9];
    int r = blockIdx.x;                 // r = b*T + t
    int b = r >> 10, t = r & 1023;
    const float* row = x + (size_t)r * CC;
    int c0 = threadIdx.x, c1 = threadIdx.x + 256;
    float v0 = row[c0], v1 = row[c1];
    float mean = block_reduce(v0 + v1, red) * (1.f / CC);
    float d0 = v0 - mean, d1 = v1 - mean;
    float var = block_reduce(d0 * d0 + d1 * d1, red) * (1.f / CC);
    float rstd = rsqrtf(var + 1e-5f);
    size_t base = ((size_t)t * BB + b) * CC;
    float y0 = d0 * rstd * gx[c0] + bx[c0];
    float y1 = d1 * rstd * gx[c1] + bx[c1];
    __nv_bfloat16 h0 = __float2bfloat16(y0);
    __nv_bfloat16 h1 = __float2bfloat16(y1);
    g_Axn_hi[base + c0] = h0;
    g_Axn_hi[base + c1] = h1;
    g_Axn_lo[base + c0] = __float2bfloat16(y0 - __bfloat162float(h0));
    g_Axn_lo[base + c1] = __float2bfloat16(y1 - __bfloat162float(h1));
}

// ---------------- weight conversion kernels ----------------
__global__ void convW_proj(const float* __restrict__ Wf, const float* __restrict__ Wb) {
    int n = blockIdx.x;  // 0..4095
    const float* src = (n < 2048) ? (Wf + (size_t)n * 512) : (Wb + (size_t)(n - 2048) * 512);
    size_t base = (size_t)n * 512;
    for (int k = threadIdx.x; k < 512; k += 256) {
        float v = src[k];
        __nv_bfloat16 h = __float2bfloat16(v);
        g_Bp_hi[base + k] = h;
        g_Bp_lo[base + k] = __float2bfloat16(v - __bfloat162float(h));
    }
}

__global__ void convW_gate(const float* __restrict__ Wg) {
    int n = blockIdx.x;  // 0..511
    size_t base = (size_t)n * 1024;
    for (int k = threadIdx.x; k < 1024; k += 256) {
        float v = Wg[base + k];
        __nv_bfloat16 h = __float2bfloat16(v);
        g_Bg_hi[base + k] = h;
        g_Bg_lo[base + k] = __float2bfloat16(v - __bfloat162float(h));
    }
}

// ---------------- HMMA GEMM: D[M,N] = A[M,K] . B[N,K]^T (bf16 hi/lo, 3 passes) ----------
template <int KDIM, int EPI>
__global__ void __launch_bounds__(256, 1) mm_kernel(const float* __restrict__ bias0,
                                                    const float* __restrict__ bias1) {
    __shared__ __nv_bfloat16 sAh[128 * PADK];
    __shared__ __nv_bfloat16 sAl[128 * PADK];
    __shared__ __nv_bfloat16 sBh[128 * PADK];
    __shared__ __nv_bfloat16 sBl[128 * PADK];

    const int tid = threadIdx.x;
    const int warp = tid >> 5, lane = tid & 31;
    const int g = lane >> 2, q = lane & 3;
    const int wm = (warp >> 1) * 32;
    const int wn = (warp & 1) * 64;
    const int m0 = blockIdx.y * 128;
    const int n0 = blockIdx.x * 128;

    const __nv_bfloat16* Ahi = (EPI == 0) ? g_Axn_hi : g_Acat_hi;
    const __nv_bfloat16* Alo = (EPI == 0) ? g_Axn_lo : g_Acat_lo;
    const __nv_bfloat16* Bhi = (EPI == 0) ? g_Bp_hi : g_Bg_hi;
    const __nv_bfloat16* Blo = (EPI == 0) ? g_Bp_lo : g_Bg_lo;

    const int r0 = tid >> 2, kq0 = (tid & 3) * 8;
    const int r1 = (tid + 256) >> 2, kq1 = ((tid + 256) & 3) * 8;
    const __nv_bfloat16* pAh0 = Ahi + (size_t)(m0 + r0) * KDIM + kq0;
    const __nv_bfloat16* pAh1 = Ahi + (size_t)(m0 + r1) * KDIM + kq1;
    const __nv_bfloat16* pAl0 = Alo + (size_t)(m0 + r0) * KDIM + kq0;
    const __nv_bfloat16* pAl1 = Alo + (size_t)(m0 + r1) * KDIM + kq1;
    const __nv_bfloat16* pBh0 = Bhi + (size_t)(n0 + r0) * KDIM + kq0;
    const __nv_bfloat16* pBh1 = Bhi + (size_t)(n0 + r1) * KDIM + kq1;
    const __nv_bfloat16* pBl0 = Blo + (size_t)(n0 + r0) * KDIM + kq0;
    const __nv_bfloat16* pBl1 = Blo + (size_t)(n0 + r1) * KDIM + kq1;

    float acc[2][8][4];
#pragma unroll
    for (int i = 0; i < 2; ++i)
#pragma unroll
        for (int j = 0; j < 8; ++j)
#pragma unroll
            for (int v = 0; v < 4; ++v) acc[i][j][v] = 0.f;

    uint4 vAh0 = *(const uint4*)pAh0, vAh1 = *(const uint4*)pAh1;
    uint4 vAl0 = *(const uint4*)pAl0, vAl1 = *(const uint4*)pAl1;
    uint4 vBh0 = *(const uint4*)pBh0, vBh1 = *(const uint4*)pBh1;
    uint4 vBl0 = *(const uint4*)pBl0, vBl1 = *(const uint4*)pBl1;

    const int NCH = KDIM / 32;
    for (int c = 0; c < NCH; ++c) {
        *(uint4*)&sAh[r0 * PADK + kq0] = vAh0;  *(uint4*)&sAh[r1 * PADK + kq1] = vAh1;
        *(uint4*)&sAl[r0 * PADK + kq0] = vAl0;  *(uint4*)&sAl[r1 * PADK + kq1] = vAl1;
        *(uint4*)&sBh[r0 * PADK + kq0] = vBh0;  *(uint4*)&sBh[r1 * PADK + kq1] = vBh1;
        *(uint4*)&sBl[r0 * PADK + kq0] = vBl0;  *(uint4*)&sBl[r1 * PADK + kq1] = vBl1;
        __syncthreads();

        if (c + 1 < NCH) {
            int koff = (c + 1) * 32;
            vAh0 = *(const uint4*)(pAh0 + koff);  vAh1 = *(const uint4*)(pAh1 + koff);
            vAl0 = *(const uint4*)(pAl0 + koff);  vAl1 = *(const uint4*)(pAl1 + koff);
            vBh0 = *(const uint4*)(pBh0 + koff);  vBh1 = *(const uint4*)(pBh1 + koff);
            vBl0 = *(const uint4*)(pBl0 + koff);  vBl1 = *(const uint4*)(pBl1 + koff);
        }

#pragma unroll
        for (int ks = 0; ks < 32; ks += 16) {
            unsigned ah[2][4], al[2][4];
#pragma unroll
            for (int mt = 0; mt < 2; ++mt) {
                int row = wm + mt * 16 + g;
                const unsigned* ph0 = (const unsigned*)&sAh[row * PADK + ks];
                const unsigned* ph1 = (const unsigned*)&sAh[(row + 8) * PADK + ks];
                ah[mt][0] = ph0[q]; ah[mt][1] = ph1[q]; ah[mt][2] = ph0[q + 4]; ah[mt][3] = ph1[q + 4];
                const unsigned* pl0 = (const unsigned*)&sAl[row * PADK + ks];
                const unsigned* pl1 = (const unsigned*)&sAl[(row + 8) * PADK + ks];
                al[mt][0] = pl0[q]; al[mt][1] = pl1[q]; al[mt][2] = pl0[q + 4]; al[mt][3] = pl1[q + 4];
            }
#pragma unroll
            for (int nt = 0; nt < 8; ++nt) {
                int nrow = wn + nt * 8 + g;
                const unsigned* pb = (const unsigned*)&sBh[nrow * PADK + ks];
                unsigned bh[2] = {pb[q], pb[q + 4]};
                const unsigned* pbl = (const unsigned*)&sBl[nrow * PADK + ks];
                unsigned bl[2] = {pbl[q], pbl[q + 4]};
#pragma unroll
                for (int mt = 0; mt < 2; ++mt) {
                    mma_bf16(acc[mt][nt], ah[mt], bh);
                    mma_bf16(acc[mt][nt], ah[mt], bl);
                    mma_bf16(acc[mt][nt], al[mt], bh);
                }
            }
        }
        __syncthreads();
    }

    if (EPI == 0) {
        const bool isf = (n0 < 2048);
        float* Y = isf ? g_xg_f : g_xg_b;
        const float* bias = isf ? bias0 : bias1;
        const int nb = (n0 & 2047) + wn;
#pragma unroll
        for (int mt = 0; mt < 2; ++mt) {
            int mrow = m0 + wm + mt * 16 + g;
#pragma unroll
            for (int nt = 0; nt < 8; ++nt) {
                int ncol = nb + nt * 8 + 2 * q;
                float bx0 = bias[ncol], bx1 = bias[ncol + 1];
                float2 v0 = make_float2(acc[mt][nt][0] + bx0, acc[mt][nt][1] + bx1);
                float2 v1 = make_float2(acc[mt][nt][2] + bx0, acc[mt][nt][3] + bx1);
                *(float2*)(Y + (size_t)mrow * 2048 + ncol) = v0;
                *(float2*)(Y + (size_t)(mrow + 8) * 2048 + ncol) = v1;
            }
        }
    } else {
#pragma unroll
        for (int mt = 0; mt < 2; ++mt) {
            int mrow = m0 + wm + mt * 16 + g;
#pragma unroll
            for (int nt = 0; nt < 8; ++nt) {
                int ncol = n0 + wn + nt * 8 + 2 * q;
                float bx0 = bias0[ncol], bx1 = bias0[ncol + 1];
#pragma unroll
                for (int hh = 0; hh < 2; ++hh) {
                    int m = mrow + hh * 8;
                    float s0 = sigf(acc[mt][nt][2 * hh + 0] + bx0);
                    float s1 = sigf(acc[mt][nt][2 * hh + 1] + bx1);
                    float2 fw = *(const float2*)(g_hs_f + (size_t)m * 512 + ncol);
                    float2 bw = *(const float2*)(g_hs_b + (size_t)m * 512 + ncol);
                    float2 o;
                    o.x = s0 * fw.x + (1.f - s0) * bw.x;
                    o.y = s1 * fw.y + (1.f - s1) * bw.y;
                    *(float2*)(g_Hout + (size_t)m * 512 + ncol) = o;
                }
            }
        }
    }
}

// ---------------- barrier reset ----------------
__global__ void reset_kernel() { g_barr[0] = 0u; g_barr[32] = 0u; }

// ---------------- persistent bidirectional LSTM scan (HMMA recurrence) -----------
// 128 CTAs: dir = bx>>6; unit slice j0 = (bx&63)*8 -> 32 gate cols (n_local = gate*8 + u)
// smem: sBh/sBl [32][SPAD]  Whh slice hi/lo (static all steps)
//       sHh/sHl [64][SPAD]  h staging (reloaded per step via cp.async from L2)
//       sG [64][34] gates fp32, sC[512] cell, sBhh[32]
__global__ void __launch_bounds__(256, 1) scan_kernel(
    const float* __restrict__ Whh_f, const float* __restrict__ bhh_f,
    const float* __restrict__ Whh_b, const float* __restrict__ bhh_b) {
    extern __shared__ char smc[];
    __nv_bfloat16* sBh = (__nv_bfloat16*)smc;              // [32][SPAD]
    __nv_bfloat16* sBl = sBh + 32 * SPAD;
    __nv_bfloat16* sHh = sBl + 32 * SPAD;                  // [64][SPAD]
    __nv_bfloat16* sHl = sHh + 64 * SPAD;
    float* sG   = (float*)(sHl + 64 * SPAD);               // [64][34]
    float* sC   = sG + 64 * 34;                            // [512]
    float* sBhh = sC + 512;                                // [32]

    const int tid  = threadIdx.x;
    const int warp = tid >> 5, lane = tid & 31;
    const int g = lane >> 2, q = lane & 3;
    const int dir = blockIdx.x >> 6;
    const int j0  = (blockIdx.x & 63) * 8;
    const int wm  = (warp & 3) * 16;     // m offset (batch)
    const int wn  = (warp >> 2) * 16;    // n offset (gate col, local)

    const float* Whh = dir ? Whh_b : Whh_f;
    const float* bhh = dir ? bhh_b : bhh_f;
    const float* xg  = dir ? g_xg_b : g_xg_f;
    float* hs        = dir ? g_hs_b : g_hs_f;
    unsigned* bar = &g_barr[dir * 32];

    unsigned sbase;
    asm("{ .reg .u64 t0; cvta.to.shared.u64 t0, %1; cvt.u32.u64 %0, t0; }" : "=r"(sbase) : "l"(smc));
    const unsigned aBh = sbase;
    const unsigned aBl = aBh + 32 * SPAD * 2;
    const unsigned aHh = aBl + 32 * SPAD * 2;
    const unsigned aHl = aHh + 64 * SPAD * 2;

    // ---- load Whh slice (hi/lo bf16) ----
    {
        int row = tid >> 3;              // 0..31 (n_local)
        int k0 = (tid & 7) * 64;
        int ngl = (row >> 3) * 512 + j0 + (row & 7);
        const float* src = Whh + (size_t)ngl * 512 + k0;
#pragma unroll
        for (int k4 = 0; k4 < 64; k4 += 4) {
            float4 v = *(const float4*)(src + k4);
            float vv[4] = {v.x, v.y, v.z, v.w};
#pragma unroll
            for (int e = 0; e < 4; ++e) {
                __nv_bfloat16 h = __float2bfloat16(vv[e]);
                sBh[row * SPAD + k0 + k4 + e] = h;
                sBl[row * SPAD + k0 + k4 + e] = __float2bfloat16(vv[e] - __bfloat162float(h));
            }
        }
    }
    if (tid < 32) sBhh[tid] = bhh[(tid >> 3) * 512 + j0 + (tid & 7)];
    for (int idx = tid; idx < 512; idx += 256) sC[idx] = 0.f;
    // zero parity-0 h exchange for our unit slice
#pragma unroll
    for (int rr = 0; rr < 2; ++rr) {
        int idx = tid + rr * 256;
        int b = idx >> 3, u = idx & 7;
        g_hx_hi[dir][0][b * 512 + j0 + u] = __float2bfloat16(0.f);
        g_hx_lo[dir][0][b * 512 + j0 + u] = __float2bfloat16(0.f);
    }
    __threadfence();
    __syncthreads();
    if (tid == 0) {
        atomicAdd(bar, 1u);
        while (*(volatile unsigned*)bar < 64u) {}
    }
    __syncthreads();

    for (int s = 0; s < TT; ++s) {
        const int t = dir ? (TT - 1 - s) : s;
        // ---- stage h (bf16 hi/lo) into smem via cp.async (L2 path) ----
        const char* hg = (const char*)g_hx_hi[dir][s & 1];
        const char* lg = (const char*)g_hx_lo[dir][s & 1];
#pragma unroll
        for (int i = 0; i < 16; ++i) {
            int idx = tid + i * 256;               // uint4 index, 0..4095
            int row = idx >> 6, c8 = (idx & 63) * 8;
            unsigned so = (unsigned)((row * SPAD + c8) * 2);
            CPASYNC16(aHh + so, hg + idx * 16);
            CPASYNC16(aHl + so, lg + idx * 16);
        }
        CPASYNC_WAIT();
        __syncthreads();

        // ---- HMMA: gates[64,32] = h[64,512] . Whh_slice[32,512]^T ----
        float acc[2][4];
#pragma unroll
        for (int nt = 0; nt < 2; ++nt)
#pragma unroll
            for (int v = 0; v < 4; ++v) acc[nt][v] = 0.f;

        const int m4 = lane >> 3;                  // matrix index 0..3
        const int arow = wm + ((m4 & 1) << 3) + (lane & 7);
        const int acolo = (m4 >> 1) << 3;
        const int brow = wn + ((m4 >> 1) << 3) + (lane & 7);
        const int bcolo = (m4 & 1) << 3;
        const unsigned aAh = aHh + (unsigned)(arow * SPAD) * 2;
        const unsigned aAl = aHl + (unsigned)(arow * SPAD) * 2;
        const unsigned aB0h = aBh + (unsigned)(brow * SPAD) * 2;
        const unsigned aB0l = aBl + (unsigned)(brow * SPAD) * 2;

#pragma unroll
        for (int ks = 0; ks < 512; ks += 16) {
            unsigned ah[4], al[4], bh[4], bl[4];
            LDSMX4(ah, aAh + (unsigned)(ks + acolo) * 2);
            LDSMX4(al, aAl + (unsigned)(ks + acolo) * 2);
            LDSMX4(bh, aB0h + (unsigned)(ks + bcolo) * 2);
            LDSMX4(bl, aB0l + (unsigned)(ks + bcolo) * 2);
#pragma unroll
            for (int nt = 0; nt < 2; ++nt) {
                mma_bf16(acc[nt], ah, bh + 2 * nt);
                mma_bf16(acc[nt], ah, bl + 2 * nt);
                mma_bf16(acc[nt], al, bh + 2 * nt);
            }
        }

        // ---- epilogue: add xg + bhh, write gates to smem ----
        const float* xgt = xg + (size_t)t * BB * G4;
#pragma unroll
        for (int nt = 0; nt < 2; ++nt) {
            int c0 = wn + nt * 8 + 2 * q;                      // n_local (even)
            int ngb = (c0 >> 3) * 512 + j0 + (c0 & 7);         // n_global
            float2 bb = *(const float2*)&sBhh[c0];
            int r0 = wm + g, r1 = r0 + 8;
            float2 x0 = *(const float2*)(xgt + (size_t)r0 * G4 + ngb);
            float2 x1 = *(const float2*)(xgt + (size_t)r1 * G4 + ngb);
            *(float2*)&sG[r0 * 34 + c0] =
                make_float2(acc[nt][0] + x0.x + bb.x, acc[nt][1] + x0.y + bb.y);
            *(float2*)&sG[r1 * 34 + c0] =
                make_float2(acc[nt][2] + x1.x + bb.x, acc[nt][3] + x1.y + bb.y);
        }
        __syncthreads();

        // ---- activation + h production ----
        __nv_bfloat16* hxh = g_hx_hi[dir][(s + 1) & 1];
        __nv_bfloat16* hxl = g_hx_lo[dir][(s + 1) & 1];
#pragma unroll
        for (int rr = 0; rr < 2; ++rr) {
            int idx = tid + rr * 256;
            int b = idx >> 3, u = idx & 7;
            float gi = sG[b * 34 + u];
            float gf = sG[b * 34 + 8 + u];
            float gg = sG[b * 34 + 16 + u];
            float go = sG[b * 34 + 24 + u];
            float cnew = sigf(gf) * sC[idx] + sigf(gi) * tanhf(gg);
            float hnew = sigf(go) * tanhf(cnew);
            sC[idx] = cnew;
            __nv_bfloat16 hh = __float2bfloat16(hnew);
            __nv_bfloat16 hl = __float2bfloat16(hnew - __bfloat162float(hh));
            int gofs = b * 512 + j0 + u;
            hxh[gofs] = hh;
            hxl[gofs] = hl;
            size_t mrow = (size_t)b * TT + t;
            hs[mrow * 512 + j0 + u] = hnew;
            size_t ar = mrow * 1024 + (size_t)dir * 512 + j0 + u;
            g_Acat_hi[ar] = hh;
            g_Acat_lo[ar] = hl;
        }
        __threadfence();
        __syncthreads();
        if (tid == 0) {
            atomicAdd(bar, 1u);
            unsigned tg = 64u * (unsigned)(s + 2);
            while (*(volatile unsigned*)bar < tg) {}
        }
        __syncthreads();
    }
}

// ---------------- final layernorm -> d_out ----------------
__global__ void ln_out_kernel(const float* __restrict__ gH,
                              const float* __restrict__ bH,
                              float* __restrict__ out) {
    __shared__ float red[9];
    int r = blockIdx.x;
    const float* row = g_Hout + (size_t)r * HH;
    int c0 = threadIdx.x, c1 = threadIdx.x + 256;
    float v0 = row[c0], v1 = row[c1];
    float mean = block_reduce(v0 + v1, red) * (1.f / HH);
    float d0 = v0 - mean, d1 = v1 - mean;
    float var = block_reduce(d0 * d0 + d1 * d1, red) * (1.f / HH);
    float rstd = rsqrtf(var + 1e-5f);
    out[(size_t)r * HH + c0] = d0 * rstd * gH[c0] + bH[c0];
    out[(size_t)r * HH + c1] = d1 * rstd * gH[c1] + bH[c1];
}

// ---------------- launch ----------------
extern "C" void kernel_launch(void* const* d_in, const int* in_sizes, int n_in,
                              void* d_out, int out_size) {
    const float* x     = (const float*)d_in[0];
    const float* Wih_f = (const float*)d_in[2];
    const float* Whh_f = (const float*)d_in[3];
    const float* bih_f = (const float*)d_in[4];
    const float* bhh_f = (const float*)d_in[5];
    const float* Wih_b = (const float*)d_in[6];
    const float* Whh_b = (const float*)d_in[7];
    const float* bih_b = (const float*)d_in[8];
    const float* bhh_b = (const float*)d_in[9];
    const float* Wg    = (const float*)d_in[10];
    const float* bg    = (const float*)d_in[11];
    const float* gx    = (const float*)d_in[12];
    const float* bx    = (const float*)d_in[13];
    const float* gH    = (const float*)d_in[14];
    const float* bH    = (const float*)d_in[15];
    float* out = (float*)d_out;

    const int scan_smem = (32 * SPAD * 2 + 64 * SPAD * 2) * 2   /* bf16 tiles */
                        + (64 * 34 + 512 + 32) * 4;             /* fp32 */
    cudaFuncSetAttribute(scan_kernel, cudaFuncAttributeMaxDynamicSharedMemorySize, scan_smem);

    ln_x_kernel<<<BB * TT, 256>>>(x, gx, bx);
    convW_proj<<<4096, 256>>>(Wih_f, Wih_b);
    convW_gate<<<512, 256>>>(Wg);
    mm_kernel<512, 0><<<dim3(4096 / 128, (BB * TT) / 128), 256>>>(bih_f, bih_b);
    reset_kernel<<<1, 1>>>();
    scan_kernel<<<128, 256, scan_smem>>>(Whh_f, bhh_f, Whh_b, bhh_b);
    mm_kernel<1024, 1><<<dim3(512 / 128, (BB * TT) / 128), 256>>>(bg, bg);
    ln_out_kernel<<<BB * TT, 256>>>(gH, bH, out);
}

// round 5
// speedup vs baseline: 2.6469x; 1.1288x over previous
#include <cuda_runtime.h>
#include <cuda_bf16.h>
#include <math.h>

#define BB   64
#define TT   1024
#define CC   512
#define HH   512
#define G4   2048
#define PADK 40   // padded k-stride for mm_kernel smem tiles
#define SPAD 520  // padded k-stride (elements) for scan smem tiles

// ---------------- scratch (static device memory; no allocs) ----------------
__device__ __nv_bfloat16 g_Axn_hi[(size_t)TT * BB * CC];   // LN(x) bf16 hi, time-major
__device__ __nv_bfloat16 g_Axn_lo[(size_t)TT * BB * CC];
__device__ __nv_bfloat16 g_Bp_hi[4096 * 512];              // stacked Wih_f | Wih_b
__device__ __nv_bfloat16 g_Bp_lo[4096 * 512];
__device__ float g_xg_f[(size_t)TT * BB * G4];             // input projection fwd [t*B+b][4H]
__device__ float g_xg_b[(size_t)TT * BB * G4];
__device__ __nv_bfloat16 g_Acat_hi[(size_t)BB * TT * 2 * HH]; // concat(fw,bw) [b*T+t][2H]
__device__ __nv_bfloat16 g_Acat_lo[(size_t)BB * TT * 2 * HH];
__device__ __nv_bfloat16 g_Bg_hi[512 * 1024];
__device__ __nv_bfloat16 g_Bg_lo[512 * 1024];
__device__ __nv_bfloat16 g_hx_hi[2][2][BB * HH];           // [dir][parity] bf16 h exchange
__device__ __nv_bfloat16 g_hx_lo[2][2][BB * HH];
__device__ float g_Hout[(size_t)BB * TT * HH];
__device__ unsigned int g_barr[64];                        // per-dir counters at [0], [32]

__device__ __forceinline__ float sigf(float x) { return 1.f / (1.f + expf(-x)); }

// ---------------- mma.sync bf16 helper ----------------
__device__ __forceinline__ void mma_bf16(float* d, const unsigned* a, const unsigned* b) {
    asm volatile(
        "mma.sync.aligned.m16n8k16.row.col.f32.bf16.bf16.f32 "
        "{%0,%1,%2,%3}, {%4,%5,%6,%7}, {%8,%9}, {%0,%1,%2,%3};"
        : "+f"(d[0]), "+f"(d[1]), "+f"(d[2]), "+f"(d[3])
        : "r"(a[0]), "r"(a[1]), "r"(a[2]), "r"(a[3]), "r"(b[0]), "r"(b[1]));
}

#define LDSMX4(R, ADDR) \
    asm volatile("ldmatrix.sync.aligned.m8n8.x4.shared.b16 {%0,%1,%2,%3}, [%4];" \
                 : "=r"((R)[0]), "=r"((R)[1]), "=r"((R)[2]), "=r"((R)[3]) : "r"(ADDR))

#define CPASYNC16(SMEM, GPTR) \
    asm volatile("cp.async.cg.shared.global [%0], [%1], 16;" :: "r"(SMEM), "l"(GPTR))

__device__ __forceinline__ void bar_release(unsigned* p) {
    asm volatile("red.release.gpu.global.add.u32 [%0], 1;" :: "l"(p) : "memory");
}
__device__ __forceinline__ unsigned ld_acq(const unsigned* p) {
    unsigned v;
    asm volatile("ld.acquire.gpu.global.u32 %0, [%1];" : "=r"(v) : "l"(p) : "memory");
    return v;
}

// ---------------- block reduce ----------------
__device__ __forceinline__ float block_reduce(float v, float* red) {
    int lane = threadIdx.x & 31, wid = threadIdx.x >> 5;
#pragma unroll
    for (int o = 16; o > 0; o >>= 1) v += __shfl_xor_sync(0xffffffffu, v, o);
    if (lane == 0) red[wid] = v;
    __syncthreads();
    if (wid == 0) {
        float w = (lane < 8) ? red[lane] : 0.f;
#pragma unroll
        for (int o = 4; o > 0; o >>= 1) w += __shfl_xor_sync(0xffffffffu, w, o);
        if (lane == 0) red[8] = w;
    }
    __syncthreads();
    float r = red[8];
    __syncthreads();
    return r;
}

// ---------------- kernel 1: layernorm(x) -> bf16 hi/lo (time-major) ----------------
__global__ void ln_x_kernel(const float* __restrict__ x,
                            const float* __restrict__ gx,
                            const float* __restrict__ bx) {
    __shared__ float red[9];
    int r = blockIdx.x;                 // r = b*T + t
    int b = r >> 10, t = r & 1023;
    const float* row = x + (size_t)r * CC;
    int c0 = threadIdx.x, c1 = threadIdx.x + 256;
    float v0 = row[c0], v1 = row[c1];
    float mean = block_reduce(v0 + v1, red) * (1.f / CC);
    float d0 = v0 - mean, d1 = v1 - mean;
    float var = block_reduce(d0 * d0 + d1 * d1, red) * (1.f / CC);
    float rstd = rsqrtf(var + 1e-5f);
    size_t base = ((size_t)t * BB + b) * CC;
    float y0 = d0 * rstd * gx[c0] + bx[c0];
    float y1 = d1 * rstd * gx[c1] + bx[c1];
    __nv_bfloat16 h0 = __float2bfloat16(y0);
    __nv_bfloat16 h1 = __float2bfloat16(y1);
    g_Axn_hi[base + c0] = h0;
    g_Axn_hi[base + c1] = h1;
    g_Axn_lo[base + c0] = __float2bfloat16(y0 - __bfloat162float(h0));
    g_Axn_lo[base + c1] = __float2bfloat16(y1 - __bfloat162float(h1));
}

// ---------------- weight conversion kernels ----------------
__global__ void convW_proj(const float* __restrict__ Wf, const float* __restrict__ Wb) {
    int n = blockIdx.x;
    const float* src = (n < 2048) ? (Wf + (size_t)n * 512) : (Wb + (size_t)(n - 2048) * 512);
    size_t base = (size_t)n * 512;
    for (int k = threadIdx.x; k < 512; k += 256) {
        float v = src[k];
        __nv_bfloat16 h = __float2bfloat16(v);
        g_Bp_hi[base + k] = h;
        g_Bp_lo[base + k] = __float2bfloat16(v - __bfloat162float(h));
    }
}

__global__ void convW_gate(const float* __restrict__ Wg) {
    int n = blockIdx.x;
    size_t base = (size_t)n * 1024;
    for (int k = threadIdx.x; k < 1024; k += 256) {
        float v = Wg[base + k];
        __nv_bfloat16 h = __float2bfloat16(v);
        g_Bg_hi[base + k] = h;
        g_Bg_lo[base + k] = __float2bfloat16(v - __bfloat162float(h));
    }
}

// ---------------- HMMA GEMM: D[M,N] = A[M,K] . B[N,K]^T (bf16 hi/lo, 3 passes) ----------
template <int KDIM, int EPI>
__global__ void __launch_bounds__(256, 1) mm_kernel(const float* __restrict__ bias0,
                                                    const float* __restrict__ bias1) {
    __shared__ __nv_bfloat16 sAh[128 * PADK];
    __shared__ __nv_bfloat16 sAl[128 * PADK];
    __shared__ __nv_bfloat16 sBh[128 * PADK];
    __shared__ __nv_bfloat16 sBl[128 * PADK];

    const int tid = threadIdx.x;
    const int warp = tid >> 5, lane = tid & 31;
    const int g = lane >> 2, q = lane & 3;
    const int wm = (warp >> 1) * 32;
    const int wn = (warp & 1) * 64;
    const int m0 = blockIdx.y * 128;
    const int n0 = blockIdx.x * 128;

    const __nv_bfloat16* Ahi = (EPI == 0) ? g_Axn_hi : g_Acat_hi;
    const __nv_bfloat16* Alo = (EPI == 0) ? g_Axn_lo : g_Acat_lo;
    const __nv_bfloat16* Bhi = (EPI == 0) ? g_Bp_hi : g_Bg_hi;
    const __nv_bfloat16* Blo = (EPI == 0) ? g_Bp_lo : g_Bg_lo;

    const int r0 = tid >> 2, kq0 = (tid & 3) * 8;
    const int r1 = (tid + 256) >> 2, kq1 = ((tid + 256) & 3) * 8;
    const __nv_bfloat16* pAh0 = Ahi + (size_t)(m0 + r0) * KDIM + kq0;
    const __nv_bfloat16* pAh1 = Ahi + (size_t)(m0 + r1) * KDIM + kq1;
    const __nv_bfloat16* pAl0 = Alo + (size_t)(m0 + r0) * KDIM + kq0;
    const __nv_bfloat16* pAl1 = Alo + (size_t)(m0 + r1) * KDIM + kq1;
    const __nv_bfloat16* pBh0 = Bhi + (size_t)(n0 + r0) * KDIM + kq0;
    const __nv_bfloat16* pBh1 = Bhi + (size_t)(n0 + r1) * KDIM + kq1;
    const __nv_bfloat16* pBl0 = Blo + (size_t)(n0 + r0) * KDIM + kq0;
    const __nv_bfloat16* pBl1 = Blo + (size_t)(n0 + r1) * KDIM + kq1;

    float acc[2][8][4];
#pragma unroll
    for (int i = 0; i < 2; ++i)
#pragma unroll
        for (int j = 0; j < 8; ++j)
#pragma unroll
            for (int v = 0; v < 4; ++v) acc[i][j][v] = 0.f;

    uint4 vAh0 = *(const uint4*)pAh0, vAh1 = *(const uint4*)pAh1;
    uint4 vAl0 = *(const uint4*)pAl0, vAl1 = *(const uint4*)pAl1;
    uint4 vBh0 = *(const uint4*)pBh0, vBh1 = *(const uint4*)pBh1;
    uint4 vBl0 = *(const uint4*)pBl0, vBl1 = *(const uint4*)pBl1;

    const int NCH = KDIM / 32;
    for (int c = 0; c < NCH; ++c) {
        *(uint4*)&sAh[r0 * PADK + kq0] = vAh0;  *(uint4*)&sAh[r1 * PADK + kq1] = vAh1;
        *(uint4*)&sAl[r0 * PADK + kq0] = vAl0;  *(uint4*)&sAl[r1 * PADK + kq1] = vAl1;
        *(uint4*)&sBh[r0 * PADK + kq0] = vBh0;  *(uint4*)&sBh[r1 * PADK + kq1] = vBh1;
        *(uint4*)&sBl[r0 * PADK + kq0] = vBl0;  *(uint4*)&sBl[r1 * PADK + kq1] = vBl1;
        __syncthreads();

        if (c + 1 < NCH) {
            int koff = (c + 1) * 32;
            vAh0 = *(const uint4*)(pAh0 + koff);  vAh1 = *(const uint4*)(pAh1 + koff);
            vAl0 = *(const uint4*)(pAl0 + koff);  vAl1 = *(const uint4*)(pAl1 + koff);
            vBh0 = *(const uint4*)(pBh0 + koff);  vBh1 = *(const uint4*)(pBh1 + koff);
            vBl0 = *(const uint4*)(pBl0 + koff);  vBl1 = *(const uint4*)(pBl1 + koff);
        }

#pragma unroll
        for (int ks = 0; ks < 32; ks += 16) {
            unsigned ah[2][4], al[2][4];
#pragma unroll
            for (int mt = 0; mt < 2; ++mt) {
                int row = wm + mt * 16 + g;
                const unsigned* ph0 = (const unsigned*)&sAh[row * PADK + ks];
                const unsigned* ph1 = (const unsigned*)&sAh[(row + 8) * PADK + ks];
                ah[mt][0] = ph0[q]; ah[mt][1] = ph1[q]; ah[mt][2] = ph0[q + 4]; ah[mt][3] = ph1[q + 4];
                const unsigned* pl0 = (const unsigned*)&sAl[row * PADK + ks];
                const unsigned* pl1 = (const unsigned*)&sAl[(row + 8) * PADK + ks];
                al[mt][0] = pl0[q]; al[mt][1] = pl1[q]; al[mt][2] = pl0[q + 4]; al[mt][3] = pl1[q + 4];
            }
#pragma unroll
            for (int nt = 0; nt < 8; ++nt) {
                int nrow = wn + nt * 8 + g;
                const unsigned* pb = (const unsigned*)&sBh[nrow * PADK + ks];
                unsigned bh[2] = {pb[q], pb[q + 4]};
                const unsigned* pbl = (const unsigned*)&sBl[nrow * PADK + ks];
                unsigned bl[2] = {pbl[q], pbl[q + 4]};
#pragma unroll
                for (int mt = 0; mt < 2; ++mt) {
                    mma_bf16(acc[mt][nt], ah[mt], bh);
                    mma_bf16(acc[mt][nt], ah[mt], bl);
                    mma_bf16(acc[mt][nt], al[mt], bh);
                }
            }
        }
        __syncthreads();
    }

    if (EPI == 0) {
        const bool isf = (n0 < 2048);
        float* Y = isf ? g_xg_f : g_xg_b;
        const float* bias = isf ? bias0 : bias1;
        const int nb = (n0 & 2047) + wn;
#pragma unroll
        for (int mt = 0; mt < 2; ++mt) {
            int mrow = m0 + wm + mt * 16 + g;
#pragma unroll
            for (int nt = 0; nt < 8; ++nt) {
                int ncol = nb + nt * 8 + 2 * q;
                float bx0 = bias[ncol], bx1 = bias[ncol + 1];
                float2 v0 = make_float2(acc[mt][nt][0] + bx0, acc[mt][nt][1] + bx1);
                float2 v1 = make_float2(acc[mt][nt][2] + bx0, acc[mt][nt][3] + bx1);
                *(float2*)(Y + (size_t)mrow * 2048 + ncol) = v0;
                *(float2*)(Y + (size_t)(mrow + 8) * 2048 + ncol) = v1;
            }
        }
    } else {
#pragma unroll
        for (int mt = 0; mt < 2; ++mt) {
            int mrow = m0 + wm + mt * 16 + g;
#pragma unroll
            for (int nt = 0; nt < 8; ++nt) {
                int ncol = n0 + wn + nt * 8 + 2 * q;
                float bx0 = bias0[ncol], bx1 = bias0[ncol + 1];
#pragma unroll
                for (int hh = 0; hh < 2; ++hh) {
                    int m = mrow + hh * 8;
                    float s0 = sigf(acc[mt][nt][2 * hh + 0] + bx0);
                    float s1 = sigf(acc[mt][nt][2 * hh + 1] + bx1);
                    size_t ab = (size_t)m * 1024 + ncol;
                    __nv_bfloat162 fh = *(const __nv_bfloat162*)(g_Acat_hi + ab);
                    __nv_bfloat162 fl = *(const __nv_bfloat162*)(g_Acat_lo + ab);
                    __nv_bfloat162 wh = *(const __nv_bfloat162*)(g_Acat_hi + ab + 512);
                    __nv_bfloat162 wl = *(const __nv_bfloat162*)(g_Acat_lo + ab + 512);
                    float fwx = __bfloat162float(fh.x) + __bfloat162float(fl.x);
                    float fwy = __bfloat162float(fh.y) + __bfloat162float(fl.y);
                    float bwx = __bfloat162float(wh.x) + __bfloat162float(wl.x);
                    float bwy = __bfloat162float(wh.y) + __bfloat162float(wl.y);
                    float2 o;
                    o.x = s0 * fwx + (1.f - s0) * bwx;
                    o.y = s1 * fwy + (1.f - s1) * bwy;
                    *(float2*)(g_Hout + (size_t)m * 512 + ncol) = o;
                }
            }
        }
    }
}

// ---------------- barrier reset ----------------
__global__ void reset_kernel() { g_barr[0] = 0u; g_barr[32] = 0u; }

// ---------------- persistent bidirectional LSTM scan (HMMA, pipelined) -----------
__global__ void __launch_bounds__(256, 1) scan_kernel(
    const float* __restrict__ Whh_f, const float* __restrict__ bhh_f,
    const float* __restrict__ Whh_b, const float* __restrict__ bhh_b) {
    extern __shared__ char smc[];
    __nv_bfloat16* sBh = (__nv_bfloat16*)smc;              // [32][SPAD] Whh hi (static)
    __nv_bfloat16* sBl = sBh + 32 * SPAD;
    __nv_bfloat16* sHh = sBl + 32 * SPAD;                  // [64][SPAD] h staging
    __nv_bfloat16* sHl = sHh + 64 * SPAD;
    float* sG   = (float*)(sHl + 64 * SPAD);               // [64][34]
    float* sC   = sG + 64 * 34;                            // [512]
    float* sBhh = sC + 512;                                // [32]

    const int tid  = threadIdx.x;
    const int warp = tid >> 5, lane = tid & 31;
    const int g = lane >> 2, q = lane & 3;
    const int dir = blockIdx.x >> 6;
    const int j0  = (blockIdx.x & 63) * 8;
    const int wm  = (warp & 3) * 16;
    const int wn  = (warp >> 2) * 16;

    const float* Whh = dir ? Whh_b : Whh_f;
    const float* bhh = dir ? bhh_b : bhh_f;
    const float* xg  = dir ? g_xg_b : g_xg_f;
    unsigned* bar = &g_barr[dir * 32];

    unsigned sbase;
    asm("{ .reg .u64 t0; cvta.to.shared.u64 t0, %1; cvt.u32.u64 %0, t0; }" : "=r"(sbase) : "l"(smc));
    const unsigned aBh = sbase;
    const unsigned aBl = aBh + 32 * SPAD * 2;
    const unsigned aHh = aBl + 32 * SPAD * 2;
    const unsigned aHl = aHh + 64 * SPAD * 2;

    // ---- load Whh slice (hi/lo bf16) ----
    {
        int row = tid >> 3;
        int k0 = (tid & 7) * 64;
        int ngl = (row >> 3) * 512 + j0 + (row & 7);
        const float* src = Whh + (size_t)ngl * 512 + k0;
#pragma unroll
        for (int k4 = 0; k4 < 64; k4 += 4) {
            float4 v = *(const float4*)(src + k4);
            float vv[4] = {v.x, v.y, v.z, v.w};
#pragma unroll
            for (int e = 0; e < 4; ++e) {
                __nv_bfloat16 h = __float2bfloat16(vv[e]);
                sBh[row * SPAD + k0 + k4 + e] = h;
                sBl[row * SPAD + k0 + k4 + e] = __float2bfloat16(vv[e] - __bfloat162float(h));
            }
        }
    }
    if (tid < 32) sBhh[tid] = bhh[(tid >> 3) * 512 + j0 + (tid & 7)];
    for (int idx = tid; idx < 512; idx += 256) sC[idx] = 0.f;
    {
        int i2 = tid * 2;
        int b = i2 >> 3, u = i2 & 7;
        __nv_bfloat162 z2; z2.x = __float2bfloat16(0.f); z2.y = z2.x;
        *(__nv_bfloat162*)&g_hx_hi[dir][0][b * 512 + j0 + u] = z2;
        *(__nv_bfloat162*)&g_hx_lo[dir][0][b * 512 + j0 + u] = z2;
    }
    __syncthreads();
    if (tid == 0) {
        bar_release(bar);
        while (ld_acq(bar) < 64u) {}
    }
    __syncthreads();

    // fragment addressing (static across steps)
    const int m4 = lane >> 3;
    const int arow = wm + ((m4 & 1) << 3) + (lane & 7);
    const int acolo = (m4 >> 1) << 3;
    const int brow = wn + ((m4 >> 1) << 3) + (lane & 7);
    const int bcolo = (m4 & 1) << 3;
    const unsigned aAh = aHh + (unsigned)(arow * SPAD) * 2;
    const unsigned aAl = aHl + (unsigned)(arow * SPAD) * 2;
    const unsigned aB0h = aBh + (unsigned)(brow * SPAD) * 2;
    const unsigned aB0l = aBl + (unsigned)(brow * SPAD) * 2;

    // epilogue column indices (static)
    const int c0a = wn + 2 * q;
    const int c0b = wn + 8 + 2 * q;
    const int ngba = (c0a >> 3) * 512 + j0 + (c0a & 7);
    const int ngbb = (c0b >> 3) * 512 + j0 + (c0b & 7);
    const int r0 = wm + g, r1 = r0 + 8;
    const float2 bb0 = *(const float2*)&sBhh[c0a];
    const float2 bb1 = *(const float2*)&sBhh[c0b];

    // activation indices (static)
    const int ab2 = (tid * 2) >> 3, au2 = (tid * 2) & 7;

    for (int s = 0; s < TT; ++s) {
        const int t = dir ? (TT - 1 - s) : s;

        // ---- xg prefetch (DRAM; consumed in epilogue) ----
        const float* xgt = xg + (size_t)t * BB * G4;
        float2 xv00 = __ldcg((const float2*)(xgt + (size_t)r0 * G4 + ngba));
        float2 xv01 = __ldcg((const float2*)(xgt + (size_t)r1 * G4 + ngba));
        float2 xv10 = __ldcg((const float2*)(xgt + (size_t)r0 * G4 + ngbb));
        float2 xv11 = __ldcg((const float2*)(xgt + (size_t)r1 * G4 + ngbb));

        // ---- stage h in two K-halves (pipelined cp.async) ----
        const char* hg = (const char*)g_hx_hi[dir][s & 1];
        const char* lg = (const char*)g_hx_lo[dir][s & 1];
#pragma unroll
        for (int ha = 0; ha < 2; ++ha) {
#pragma unroll
            for (int i = 0; i < 8; ++i) {
                int idx = tid + i * 256;               // 0..2047
                int row = idx >> 5;
                int c8 = (idx & 31) * 8 + ha * 256;
                unsigned so = (unsigned)((row * SPAD + c8) * 2);
                int go = (row * 512 + c8) * 2;
                CPASYNC16(aHh + so, hg + go);
                CPASYNC16(aHl + so, lg + go);
            }
            asm volatile("cp.async.commit_group;");
        }
        asm volatile("cp.async.wait_group 1;" ::: "memory");
        __syncthreads();

        float acc[2][4];
#pragma unroll
        for (int nt = 0; nt < 2; ++nt)
#pragma unroll
            for (int v = 0; v < 4; ++v) acc[nt][v] = 0.f;

#pragma unroll
        for (int ks = 0; ks < 256; ks += 16) {
            unsigned ah[4], al[4], bh2[4], bl2[4];
            LDSMX4(ah, aAh + (unsigned)(ks + acolo) * 2);
            LDSMX4(al, aAl + (unsigned)(ks + acolo) * 2);
            LDSMX4(bh2, aB0h + (unsigned)(ks + bcolo) * 2);
            LDSMX4(bl2, aB0l + (unsigned)(ks + bcolo) * 2);
#pragma unroll
            for (int nt = 0; nt < 2; ++nt) {
                mma_bf16(acc[nt], ah, bh2 + 2 * nt);
                mma_bf16(acc[nt], ah, bl2 + 2 * nt);
                mma_bf16(acc[nt], al, bh2 + 2 * nt);
            }
        }
        asm volatile("cp.async.wait_group 0;" ::: "memory");
        __syncthreads();
#pragma unroll
        for (int ks = 256; ks < 512; ks += 16) {
            unsigned ah[4], al[4], bh2[4], bl2[4];
            LDSMX4(ah, aAh + (unsigned)(ks + acolo) * 2);
            LDSMX4(al, aAl + (unsigned)(ks + acolo) * 2);
            LDSMX4(bh2, aB0h + (unsigned)(ks + bcolo) * 2);
            LDSMX4(bl2, aB0l + (unsigned)(ks + bcolo) * 2);
#pragma unroll
            for (int nt = 0; nt < 2; ++nt) {
                mma_bf16(acc[nt], ah, bh2 + 2 * nt);
                mma_bf16(acc[nt], ah, bl2 + 2 * nt);
                mma_bf16(acc[nt], al, bh2 + 2 * nt);
            }
        }

        // ---- epilogue: add xg + bhh, write gates to smem ----
        *(float2*)&sG[r0 * 34 + c0a] =
            make_float2(acc[0][0] + xv00.x + bb0.x, acc[0][1] + xv00.y + bb0.y);
        *(float2*)&sG[r1 * 34 + c0a] =
            make_float2(acc[0][2] + xv01.x + bb0.x, acc[0][3] + xv01.y + bb0.y);
        *(float2*)&sG[r0 * 34 + c0b] =
            make_float2(acc[1][0] + xv10.x + bb1.x, acc[1][1] + xv10.y + bb1.y);
        *(float2*)&sG[r1 * 34 + c0b] =
            make_float2(acc[1][2] + xv11.x + bb1.x, acc[1][3] + xv11.y + bb1.y);
        __syncthreads();

        // ---- activation + h production (2 consecutive states per thread) ----
        {
            float2 gi = *(const float2*)&sG[ab2 * 34 + au2];
            float2 gf = *(const float2*)&sG[ab2 * 34 + 8 + au2];
            float2 gg = *(const float2*)&sG[ab2 * 34 + 16 + au2];
            float2 go = *(const float2*)&sG[ab2 * 34 + 24 + au2];
            float2 cold = *(const float2*)&sC[tid * 2];
            float cn0 = sigf(gf.x) * cold.x + sigf(gi.x) * tanhf(gg.x);
            float cn1 = sigf(gf.y) * cold.y + sigf(gi.y) * tanhf(gg.y);
            float hn0 = sigf(go.x) * tanhf(cn0);
            float hn1 = sigf(go.y) * tanhf(cn1);
            *(float2*)&sC[tid * 2] = make_float2(cn0, cn1);
            __nv_bfloat162 hh, hl;
            hh.x = __float2bfloat16(hn0);
            hh.y = __float2bfloat16(hn1);
            hl.x = __float2bfloat16(hn0 - __bfloat162float(hh.x));
            hl.y = __float2bfloat16(hn1 - __bfloat162float(hh.y));
            int gofs = ab2 * 512 + j0 + au2;
            *(__nv_bfloat162*)&g_hx_hi[dir][(s + 1) & 1][gofs] = hh;
            *(__nv_bfloat162*)&g_hx_lo[dir][(s + 1) & 1][gofs] = hl;
            size_t ar = ((size_t)ab2 * TT + t) * 1024 + (size_t)dir * 512 + j0 + au2;
            *(__nv_bfloat162*)&g_Acat_hi[ar] = hh;
            *(__nv_bfloat162*)&g_Acat_lo[ar] = hl;
        }
        __syncthreads();
        if (tid == 0) {
            bar_release(bar);
            unsigned tg = 64u * (unsigned)(s + 2);
            while (ld_acq(bar) < tg) {}
        }
        __syncthreads();
    }
}

// ---------------- final layernorm -> d_out ----------------
__global__ void ln_out_kernel(const float* __restrict__ gH,
                              const float* __restrict__ bH,
                              float* __restrict__ out) {
    __shared__ float red[9];
    int r = blockIdx.x;
    const float* row = g_Hout + (size_t)r * HH;
    int c0 = threadIdx.x, c1 = threadIdx.x + 256;
    float v0 = row[c0], v1 = row[c1];
    float mean = block_reduce(v0 + v1, red) * (1.f / HH);
    float d0 = v0 - mean, d1 = v1 - mean;
    float var = block_reduce(d0 * d0 + d1 * d1, red) * (1.f / HH);
    float rstd = rsqrtf(var + 1e-5f);
    out[(size_t)r * HH + c0] = d0 * rstd * gH[c0] + bH[c0];
    out[(size_t)r * HH + c1] = d1 * rstd * gH[c1] + bH[c1];
}

// ---------------- launch ----------------
extern "C" void kernel_launch(void* const* d_in, const int* in_sizes, int n_in,
                              void* d_out, int out_size) {
    const float* x     = (const float*)d_in[0];
    const float* Wih_f = (const float*)d_in[2];
    const float* Whh_f = (const float*)d_in[3];
    const float* bih_f = (const float*)d_in[4];
    const float* bhh_f = (const float*)d_in[5];
    const float* Wih_b = (const float*)d_in[6];
    const float* Whh_b = (const float*)d_in[7];
    const float* bih_b = (const float*)d_in[8];
    const float* bhh_b = (const float*)d_in[9];
    const float* Wg    = (const float*)d_in[10];
    const float* bg    = (const float*)d_in[11];
    const float* gx    = (const float*)d_in[12];
    const float* bx    = (const float*)d_in[13];
    const float* gH    = (const float*)d_in[14];
    const float* bH    = (const float*)d_in[15];
    float* out = (float*)d_out;

    const int scan_smem = (32 * SPAD * 2 + 64 * SPAD * 2) * 2
                        + (64 * 34 + 512 + 32) * 4;
    cudaFuncSetAttribute(scan_kernel, cudaFuncAttributeMaxDynamicSharedMemorySize, scan_smem);

    ln_x_kernel<<<BB * TT, 256>>>(x, gx, bx);
    convW_proj<<<4096, 256>>>(Wih_f, Wih_b);
    convW_gate<<<512, 256>>>(Wg);
    mm_kernel<512, 0><<<dim3(4096 / 128, (BB * TT) / 128), 256>>>(bih_f, bih_b);
    reset_kernel<<<1, 1>>>();
    scan_kernel<<<128, 256, scan_smem>>>(Whh_f, bhh_f, Whh_b, bhh_b);
    mm_kernel<1024, 1><<<dim3(512 / 128, (BB * TT) / 128), 256>>>(bg, bg);
    ln_out_kernel<<<BB * TT, 256>>>(gH, bH, out);
}

// round 6
// speedup vs baseline: 2.9528x; 1.1156x over previous
#include <cuda_runtime.h>
#include <cuda_bf16.h>
#include <math.h>

#define BB   64
#define TT   1024
#define CC   512
#define HH   512
#define G4   2048
#define PADK 40   // padded k-stride for mm_kernel smem tiles
#define SPAD 520  // padded k-stride (elements) for scan smem tiles

// ---------------- scratch (static device memory; no allocs) ----------------
__device__ __nv_bfloat16 g_Axn_hi[(size_t)TT * BB * CC];
__device__ __nv_bfloat16 g_Axn_lo[(size_t)TT * BB * CC];
__device__ __nv_bfloat16 g_Bp_hi[4096 * 512];
__device__ __nv_bfloat16 g_Bp_lo[4096 * 512];
__device__ float g_xg_f[(size_t)TT * BB * G4];
__device__ float g_xg_b[(size_t)TT * BB * G4];
__device__ __nv_bfloat16 g_Acat_hi[(size_t)BB * TT * 2 * HH];
__device__ __nv_bfloat16 g_Acat_lo[(size_t)BB * TT * 2 * HH];
__device__ __nv_bfloat16 g_Bg_hi[512 * 1024];
__device__ __nv_bfloat16 g_Bg_lo[512 * 1024];
__device__ __nv_bfloat16 g_hx_hi[2][2][BB * HH];           // [dir][parity]
__device__ __nv_bfloat16 g_hx_lo[2][2][BB * HH];
__device__ float g_Hout[(size_t)BB * TT * HH];
__device__ unsigned int g_barr[128];                       // counters at 0,32,64,96

__device__ __forceinline__ float sigf(float x) { return 1.f / (1.f + expf(-x)); }

// ---------------- mma.sync bf16 helper ----------------
__device__ __forceinline__ void mma_bf16(float* d, const unsigned* a, const unsigned* b) {
    asm volatile(
        "mma.sync.aligned.m16n8k16.row.col.f32.bf16.bf16.f32 "
        "{%0,%1,%2,%3}, {%4,%5,%6,%7}, {%8,%9}, {%0,%1,%2,%3};"
        : "+f"(d[0]), "+f"(d[1]), "+f"(d[2]), "+f"(d[3])
        : "r"(a[0]), "r"(a[1]), "r"(a[2]), "r"(a[3]), "r"(b[0]), "r"(b[1]));
}

#define LDSMX4(R, ADDR) \
    asm volatile("ldmatrix.sync.aligned.m8n8.x4.shared.b16 {%0,%1,%2,%3}, [%4];" \
                 : "=r"((R)[0]), "=r"((R)[1]), "=r"((R)[2]), "=r"((R)[3]) : "r"(ADDR))

#define CPASYNC16(SMEM, GPTR) \
    asm volatile("cp.async.cg.shared.global [%0], [%1], 16;" :: "r"(SMEM), "l"(GPTR))

__device__ __forceinline__ void bar_release(unsigned* p) {
    asm volatile("red.release.gpu.global.add.u32 [%0], 1;" :: "l"(p) : "memory");
}
__device__ __forceinline__ unsigned ld_acq(const unsigned* p) {
    unsigned v;
    asm volatile("ld.acquire.gpu.global.u32 %0, [%1];" : "=r"(v) : "l"(p) : "memory");
    return v;
}

// ---------------- block reduce ----------------
__device__ __forceinline__ float block_reduce(float v, float* red) {
    int lane = threadIdx.x & 31, wid = threadIdx.x >> 5;
#pragma unroll
    for (int o = 16; o > 0; o >>= 1) v += __shfl_xor_sync(0xffffffffu, v, o);
    if (lane == 0) red[wid] = v;
    __syncthreads();
    if (wid == 0) {
        float w = (lane < 8) ? red[lane] : 0.f;
#pragma unroll
        for (int o = 4; o > 0; o >>= 1) w += __shfl_xor_sync(0xffffffffu, w, o);
        if (lane == 0) red[8] = w;
    }
    __syncthreads();
    float r = red[8];
    __syncthreads();
    return r;
}

// ---------------- kernel 1: layernorm(x) -> bf16 hi/lo (time-major) ----------------
__global__ void ln_x_kernel(const float* __restrict__ x,
                            const float* __restrict__ gx,
                            const float* __restrict__ bx) {
    __shared__ float red[9];
    int r = blockIdx.x;
    int b = r >> 10, t = r & 1023;
    const float* row = x + (size_t)r * CC;
    int c0 = threadIdx.x, c1 = threadIdx.x + 256;
    float v0 = row[c0], v1 = row[c1];
    float mean = block_reduce(v0 + v1, red) * (1.f / CC);
    float d0 = v0 - mean, d1 = v1 - mean;
    float var = block_reduce(d0 * d0 + d1 * d1, red) * (1.f / CC);
    float rstd = rsqrtf(var + 1e-5f);
    size_t base = ((size_t)t * BB + b) * CC;
    float y0 = d0 * rstd * gx[c0] + bx[c0];
    float y1 = d1 * rstd * gx[c1] + bx[c1];
    __nv_bfloat16 h0 = __float2bfloat16(y0);
    __nv_bfloat16 h1 = __float2bfloat16(y1);
    g_Axn_hi[base + c0] = h0;
    g_Axn_hi[base + c1] = h1;
    g_Axn_lo[base + c0] = __float2bfloat16(y0 - __bfloat162float(h0));
    g_Axn_lo[base + c1] = __float2bfloat16(y1 - __bfloat162float(h1));
}

// ---------------- weight conversion kernels ----------------
__global__ void convW_proj(const float* __restrict__ Wf, const float* __restrict__ Wb) {
    int n = blockIdx.x;
    const float* src = (n < 2048) ? (Wf + (size_t)n * 512) : (Wb + (size_t)(n - 2048) * 512);
    size_t base = (size_t)n * 512;
    for (int k = threadIdx.x; k < 512; k += 256) {
        float v = src[k];
        __nv_bfloat16 h = __float2bfloat16(v);
        g_Bp_hi[base + k] = h;
        g_Bp_lo[base + k] = __float2bfloat16(v - __bfloat162float(h));
    }
}

__global__ void convW_gate(const float* __restrict__ Wg) {
    int n = blockIdx.x;
    size_t base = (size_t)n * 1024;
    for (int k = threadIdx.x; k < 1024; k += 256) {
        float v = Wg[base + k];
        __nv_bfloat16 h = __float2bfloat16(v);
        g_Bg_hi[base + k] = h;
        g_Bg_lo[base + k] = __float2bfloat16(v - __bfloat162float(h));
    }
}

// ---------------- HMMA GEMM: D[M,N] = A[M,K] . B[N,K]^T (bf16 hi/lo, 3 passes) ----------
template <int KDIM, int EPI>
__global__ void __launch_bounds__(256, 1) mm_kernel(const float* __restrict__ bias0,
                                                    const float* __restrict__ bias1) {
    __shared__ __nv_bfloat16 sAh[128 * PADK];
    __shared__ __nv_bfloat16 sAl[128 * PADK];
    __shared__ __nv_bfloat16 sBh[128 * PADK];
    __shared__ __nv_bfloat16 sBl[128 * PADK];

    const int tid = threadIdx.x;
    const int warp = tid >> 5, lane = tid & 31;
    const int g = lane >> 2, q = lane & 3;
    const int wm = (warp >> 1) * 32;
    const int wn = (warp & 1) * 64;
    const int m0 = blockIdx.y * 128;
    const int n0 = blockIdx.x * 128;

    const __nv_bfloat16* Ahi = (EPI == 0) ? g_Axn_hi : g_Acat_hi;
    const __nv_bfloat16* Alo = (EPI == 0) ? g_Axn_lo : g_Acat_lo;
    const __nv_bfloat16* Bhi = (EPI == 0) ? g_Bp_hi : g_Bg_hi;
    const __nv_bfloat16* Blo = (EPI == 0) ? g_Bp_lo : g_Bg_lo;

    const int r0 = tid >> 2, kq0 = (tid & 3) * 8;
    const int r1 = (tid + 256) >> 2, kq1 = ((tid + 256) & 3) * 8;
    const __nv_bfloat16* pAh0 = Ahi + (size_t)(m0 + r0) * KDIM + kq0;
    const __nv_bfloat16* pAh1 = Ahi + (size_t)(m0 + r1) * KDIM + kq1;
    const __nv_bfloat16* pAl0 = Alo + (size_t)(m0 + r0) * KDIM + kq0;
    const __nv_bfloat16* pAl1 = Alo + (size_t)(m0 + r1) * KDIM + kq1;
    const __nv_bfloat16* pBh0 = Bhi + (size_t)(n0 + r0) * KDIM + kq0;
    const __nv_bfloat16* pBh1 = Bhi + (size_t)(n0 + r1) * KDIM + kq1;
    const __nv_bfloat16* pBl0 = Blo + (size_t)(n0 + r0) * KDIM + kq0;
    const __nv_bfloat16* pBl1 = Blo + (size_t)(n0 + r1) * KDIM + kq1;

    float acc[2][8][4];
#pragma unroll
    for (int i = 0; i < 2; ++i)
#pragma unroll
        for (int j = 0; j < 8; ++j)
#pragma unroll
            for (int v = 0; v < 4; ++v) acc[i][j][v] = 0.f;

    uint4 vAh0 = *(const uint4*)pAh0, vAh1 = *(const uint4*)pAh1;
    uint4 vAl0 = *(const uint4*)pAl0, vAl1 = *(const uint4*)pAl1;
    uint4 vBh0 = *(const uint4*)pBh0, vBh1 = *(const uint4*)pBh1;
    uint4 vBl0 = *(const uint4*)pBl0, vBl1 = *(const uint4*)pBl1;

    const int NCH = KDIM / 32;
    for (int c = 0; c < NCH; ++c) {
        *(uint4*)&sAh[r0 * PADK + kq0] = vAh0;  *(uint4*)&sAh[r1 * PADK + kq1] = vAh1;
        *(uint4*)&sAl[r0 * PADK + kq0] = vAl0;  *(uint4*)&sAl[r1 * PADK + kq1] = vAl1;
        *(uint4*)&sBh[r0 * PADK + kq0] = vBh0;  *(uint4*)&sBh[r1 * PADK + kq1] = vBh1;
        *(uint4*)&sBl[r0 * PADK + kq0] = vBl0;  *(uint4*)&sBl[r1 * PADK + kq1] = vBl1;
        __syncthreads();

        if (c + 1 < NCH) {
            int koff = (c + 1) * 32;
            vAh0 = *(const uint4*)(pAh0 + koff);  vAh1 = *(const uint4*)(pAh1 + koff);
            vAl0 = *(const uint4*)(pAl0 + koff);  vAl1 = *(const uint4*)(pAl1 + koff);
            vBh0 = *(const uint4*)(pBh0 + koff);  vBh1 = *(const uint4*)(pBh1 + koff);
            vBl0 = *(const uint4*)(pBl0 + koff);  vBl1 = *(const uint4*)(pBl1 + koff);
        }

#pragma unroll
        for (int ks = 0; ks < 32; ks += 16) {
            unsigned ah[2][4], al[2][4];
#pragma unroll
            for (int mt = 0; mt < 2; ++mt) {
                int row = wm + mt * 16 + g;
                const unsigned* ph0 = (const unsigned*)&sAh[row * PADK + ks];
                const unsigned* ph1 = (const unsigned*)&sAh[(row + 8) * PADK + ks];
                ah[mt][0] = ph0[q]; ah[mt][1] = ph1[q]; ah[mt][2] = ph0[q + 4]; ah[mt][3] = ph1[q + 4];
                const unsigned* pl0 = (const unsigned*)&sAl[row * PADK + ks];
                const unsigned* pl1 = (const unsigned*)&sAl[(row + 8) * PADK + ks];
                al[mt][0] = pl0[q]; al[mt][1] = pl1[q]; al[mt][2] = pl0[q + 4]; al[mt][3] = pl1[q + 4];
            }
#pragma unroll
            for (int nt = 0; nt < 8; ++nt) {
                int nrow = wn + nt * 8 + g;
                const unsigned* pb = (const unsigned*)&sBh[nrow * PADK + ks];
                unsigned bh[2] = {pb[q], pb[q + 4]};
                const unsigned* pbl = (const unsigned*)&sBl[nrow * PADK + ks];
                unsigned bl[2] = {pbl[q], pbl[q + 4]};
#pragma unroll
                for (int mt = 0; mt < 2; ++mt) {
                    mma_bf16(acc[mt][nt], ah[mt], bh);
                    mma_bf16(acc[mt][nt], ah[mt], bl);
                    mma_bf16(acc[mt][nt], al[mt], bh);
                }
            }
        }
        __syncthreads();
    }

    if (EPI == 0) {
        const bool isf = (n0 < 2048);
        float* Y = isf ? g_xg_f : g_xg_b;
        const float* bias = isf ? bias0 : bias1;
        const int nb = (n0 & 2047) + wn;
#pragma unroll
        for (int mt = 0; mt < 2; ++mt) {
            int mrow = m0 + wm + mt * 16 + g;
#pragma unroll
            for (int nt = 0; nt < 8; ++nt) {
                int ncol = nb + nt * 8 + 2 * q;
                float bx0 = bias[ncol], bx1 = bias[ncol + 1];
                float2 v0 = make_float2(acc[mt][nt][0] + bx0, acc[mt][nt][1] + bx1);
                float2 v1 = make_float2(acc[mt][nt][2] + bx0, acc[mt][nt][3] + bx1);
                *(float2*)(Y + (size_t)mrow * 2048 + ncol) = v0;
                *(float2*)(Y + (size_t)(mrow + 8) * 2048 + ncol) = v1;
            }
        }
    } else {
#pragma unroll
        for (int mt = 0; mt < 2; ++mt) {
            int mrow = m0 + wm + mt * 16 + g;
#pragma unroll
            for (int nt = 0; nt < 8; ++nt) {
                int ncol = n0 + wn + nt * 8 + 2 * q;
                float bx0 = bias0[ncol], bx1 = bias0[ncol + 1];
#pragma unroll
                for (int hh = 0; hh < 2; ++hh) {
                    int m = mrow + hh * 8;
                    float s0 = sigf(acc[mt][nt][2 * hh + 0] + bx0);
                    float s1 = sigf(acc[mt][nt][2 * hh + 1] + bx1);
                    size_t ab = (size_t)m * 1024 + ncol;
                    __nv_bfloat162 fh = *(const __nv_bfloat162*)(g_Acat_hi + ab);
                    __nv_bfloat162 fl = *(const __nv_bfloat162*)(g_Acat_lo + ab);
                    __nv_bfloat162 wh = *(const __nv_bfloat162*)(g_Acat_hi + ab + 512);
                    __nv_bfloat162 wl = *(const __nv_bfloat162*)(g_Acat_lo + ab + 512);
                    float fwx = __bfloat162float(fh.x) + __bfloat162float(fl.x);
                    float fwy = __bfloat162float(fh.y) + __bfloat162float(fl.y);
                    float bwx = __bfloat162float(wh.x) + __bfloat162float(wl.x);
                    float bwy = __bfloat162float(wh.y) + __bfloat162float(wl.y);
                    float2 o;
                    o.x = s0 * fwx + (1.f - s0) * bwx;
                    o.y = s1 * fwy + (1.f - s1) * bwy;
                    *(float2*)(g_Hout + (size_t)m * 512 + ncol) = o;
                }
            }
        }
    }
}

// ---------------- barrier reset ----------------
__global__ void reset_kernel() {
    g_barr[0] = 0u; g_barr[32] = 0u; g_barr[64] = 0u; g_barr[96] = 0u;
}

// ---------------- persistent bidirectional LSTM scan (HMMA, batch-split) -----------
// 128 CTAs: dir = bx>>6, grp = (bx>>5)&1 (batch group of 32), sl = bx&31 -> 16 units.
// Each CTA: gates[32 batches, 64 cols] = h[32,512] . Whh_slice[64,512]^T (+xg+bhh).
// Only syncs with the 31 other CTAs of its (dir,grp).
__global__ void __launch_bounds__(256, 1) scan_kernel(
    const float* __restrict__ Whh_f, const float* __restrict__ bhh_f,
    const float* __restrict__ Whh_b, const float* __restrict__ bhh_b) {
    extern __shared__ char smc[];
    __nv_bfloat16* sBh = (__nv_bfloat16*)smc;              // [64][SPAD] Whh hi (static)
    __nv_bfloat16* sBl = sBh + 64 * SPAD;
    __nv_bfloat16* sHh = sBl + 64 * SPAD;                  // [32][SPAD] h staging
    __nv_bfloat16* sHl = sHh + 32 * SPAD;
    float* sG   = (float*)(sHl + 32 * SPAD);               // [32][66]
    float* sC   = sG + 32 * 66;                            // [512]
    float* sBhh = sC + 512;                                // [64]

    const int tid  = threadIdx.x;
    const int warp = tid >> 5, lane = tid & 31;
    const int g = lane >> 2, q = lane & 3;
    const int dir = blockIdx.x >> 6;
    const int grp = (blockIdx.x >> 5) & 1;
    const int j0  = (blockIdx.x & 31) * 16;   // 16 units
    const int b0g = grp * 32;                 // batch offset
    const int wm  = (warp & 1) * 16;          // m (batch) offset in [0,32)
    const int wn  = (warp >> 1) * 16;         // n (gate col) offset in [0,64)

    const float* Whh = dir ? Whh_b : Whh_f;
    const float* bhh = dir ? bhh_b : bhh_f;
    const float* xg  = dir ? g_xg_b : g_xg_f;
    unsigned* bar = &g_barr[(dir * 2 + grp) * 32];

    unsigned sbase;
    asm("{ .reg .u64 t0; cvta.to.shared.u64 t0, %1; cvt.u32.u64 %0, t0; }" : "=r"(sbase) : "l"(smc));
    const unsigned aBh = sbase;
    const unsigned aBl = aBh + 64 * SPAD * 2;
    const unsigned aHh = aBl + 64 * SPAD * 2;
    const unsigned aHl = aHh + 32 * SPAD * 2;

    // ---- load Whh slice [64 cols][512] hi/lo ----
    {
        int row = tid >> 2;                   // 0..63 (n_local)
        int k0 = (tid & 3) * 128;             // 4 threads per row
        int ngl = (row >> 4) * 512 + j0 + (row & 15);
        const float* src = Whh + (size_t)ngl * 512 + k0;
#pragma unroll
        for (int k4 = 0; k4 < 128; k4 += 4) {
            float4 v = *(const float4*)(src + k4);
            float vv[4] = {v.x, v.y, v.z, v.w};
#pragma unroll
            for (int e = 0; e < 4; ++e) {
                __nv_bfloat16 h = __float2bfloat16(vv[e]);
                sBh[row * SPAD + k0 + k4 + e] = h;
                sBl[row * SPAD + k0 + k4 + e] = __float2bfloat16(vv[e] - __bfloat162float(h));
            }
        }
    }
    if (tid < 64) sBhh[tid] = bhh[(tid >> 4) * 512 + j0 + (tid & 15)];
    for (int idx = tid; idx < 512; idx += 256) sC[idx] = 0.f;
    {
        int i2 = tid * 2;                      // 0..510
        int bl2 = i2 >> 4, u = i2 & 15;
        __nv_bfloat162 z2; z2.x = __float2bfloat16(0.f); z2.y = z2.x;
        *(__nv_bfloat162*)&g_hx_hi[dir][0][(b0g + bl2) * 512 + j0 + u] = z2;
        *(__nv_bfloat162*)&g_hx_lo[dir][0][(b0g + bl2) * 512 + j0 + u] = z2;
    }
    __syncthreads();
    if (tid == 0) {
        bar_release(bar);
        while (ld_acq(bar) < 32u) {}
    }
    __syncthreads();

    // fragment addressing (static across steps)
    const int m4 = lane >> 3;
    const int arow = wm + ((m4 & 1) << 3) + (lane & 7);
    const int acolo = (m4 >> 1) << 3;
    const int brow = wn + ((m4 >> 1) << 3) + (lane & 7);
    const int bcolo = (m4 & 1) << 3;
    const unsigned aAh = aHh + (unsigned)(arow * SPAD) * 2;
    const unsigned aAl = aHl + (unsigned)(arow * SPAD) * 2;
    const unsigned aB0h = aBh + (unsigned)(brow * SPAD) * 2;
    const unsigned aB0l = aBl + (unsigned)(brow * SPAD) * 2;

    // epilogue indices (static)
    const int c0a = wn + 2 * q;
    const int c0b = wn + 8 + 2 * q;
    const int ngba = (c0a >> 4) * 512 + j0 + (c0a & 15);
    const int ngbb = (c0b >> 4) * 512 + j0 + (c0b & 15);
    const int r0 = wm + g, r1 = r0 + 8;       // local batch rows
    const float2 bb0 = *(const float2*)&sBhh[c0a];
    const float2 bb1 = *(const float2*)&sBhh[c0b];

    // activation indices (static)
    const int ab2 = (tid * 2) >> 4, au2 = (tid * 2) & 15;

    for (int s = 0; s < TT; ++s) {
        const int t = dir ? (TT - 1 - s) : s;

        // ---- xg prefetch (DRAM; consumed in epilogue) ----
        const float* xgt = xg + (size_t)t * BB * G4;
        float2 xv00 = __ldcg((const float2*)(xgt + (size_t)(b0g + r0) * G4 + ngba));
        float2 xv01 = __ldcg((const float2*)(xgt + (size_t)(b0g + r1) * G4 + ngba));
        float2 xv10 = __ldcg((const float2*)(xgt + (size_t)(b0g + r0) * G4 + ngbb));
        float2 xv11 = __ldcg((const float2*)(xgt + (size_t)(b0g + r1) * G4 + ngbb));

        // ---- stage h[32,512] hi/lo in two K-halves (pipelined cp.async) ----
        const char* hg = (const char*)&g_hx_hi[dir][s & 1][b0g * 512];
        const char* lg = (const char*)&g_hx_lo[dir][s & 1][b0g * 512];
#pragma unroll
        for (int ha = 0; ha < 2; ++ha) {
#pragma unroll
            for (int i = 0; i < 4; ++i) {
                int idx = tid + i * 256;               // 0..1023
                int row = idx >> 5;                    // 0..31
                int c8 = (idx & 31) * 8 + ha * 256;
                unsigned so = (unsigned)((row * SPAD + c8) * 2);
                int go = (row * 512 + c8) * 2;
                CPASYNC16(aHh + so, hg + go);
                CPASYNC16(aHl + so, lg + go);
            }
            asm volatile("cp.async.commit_group;");
        }
        asm volatile("cp.async.wait_group 1;" ::: "memory");
        __syncthreads();

        float acc[2][4];
#pragma unroll
        for (int nt = 0; nt < 2; ++nt)
#pragma unroll
            for (int v = 0; v < 4; ++v) acc[nt][v] = 0.f;

#pragma unroll
        for (int ks = 0; ks < 256; ks += 16) {
            unsigned ah[4], al[4], bh2[4], bl2[4];
            LDSMX4(ah, aAh + (unsigned)(ks + acolo) * 2);
            LDSMX4(al, aAl + (unsigned)(ks + acolo) * 2);
            LDSMX4(bh2, aB0h + (unsigned)(ks + bcolo) * 2);
            LDSMX4(bl2, aB0l + (unsigned)(ks + bcolo) * 2);
#pragma unroll
            for (int nt = 0; nt < 2; ++nt) {
                mma_bf16(acc[nt], ah, bh2 + 2 * nt);
                mma_bf16(acc[nt], ah, bl2 + 2 * nt);
                mma_bf16(acc[nt], al, bh2 + 2 * nt);
            }
        }
        asm volatile("cp.async.wait_group 0;" ::: "memory");
        __syncthreads();
#pragma unroll
        for (int ks = 256; ks < 512; ks += 16) {
            unsigned ah[4], al[4], bh2[4], bl2[4];
            LDSMX4(ah, aAh + (unsigned)(ks + acolo) * 2);
            LDSMX4(al, aAl + (unsigned)(ks + acolo) * 2);
            LDSMX4(bh2, aB0h + (unsigned)(ks + bcolo) * 2);
            LDSMX4(bl2, aB0l + (unsigned)(ks + bcolo) * 2);
#pragma unroll
            for (int nt = 0; nt < 2; ++nt) {
                mma_bf16(acc[nt], ah, bh2 + 2 * nt);
                mma_bf16(acc[nt], ah, bl2 + 2 * nt);
                mma_bf16(acc[nt], al, bh2 + 2 * nt);
            }
        }

        // ---- epilogue: add xg + bhh, write gates to smem ----
        *(float2*)&sG[r0 * 66 + c0a] =
            make_float2(acc[0][0] + xv00.x + bb0.x, acc[0][1] + xv00.y + bb0.y);
        *(float2*)&sG[r1 * 66 + c0a] =
            make_float2(acc[0][2] + xv01.x + bb0.x, acc[0][3] + xv01.y + bb0.y);
        *(float2*)&sG[r0 * 66 + c0b] =
            make_float2(acc[1][0] + xv10.x + bb1.x, acc[1][1] + xv10.y + bb1.y);
        *(float2*)&sG[r1 * 66 + c0b] =
            make_float2(acc[1][2] + xv11.x + bb1.x, acc[1][3] + xv11.y + bb1.y);
        __syncthreads();

        // ---- activation + h production (2 consecutive states per thread) ----
        {
            float2 gi = *(const float2*)&sG[ab2 * 66 + au2];
            float2 gf = *(const float2*)&sG[ab2 * 66 + 16 + au2];
            float2 gg = *(const float2*)&sG[ab2 * 66 + 32 + au2];
            float2 go = *(const float2*)&sG[ab2 * 66 + 48 + au2];
            float2 cold = *(const float2*)&sC[tid * 2];
            float cn0 = sigf(gf.x) * cold.x + sigf(gi.x) * tanhf(gg.x);
            float cn1 = sigf(gf.y) * cold.y + sigf(gi.y) * tanhf(gg.y);
            float hn0 = sigf(go.x) * tanhf(cn0);
            float hn1 = sigf(go.y) * tanhf(cn1);
            *(float2*)&sC[tid * 2] = make_float2(cn0, cn1);
            __nv_bfloat162 hh, hl;
            hh.x = __float2bfloat16(hn0);
            hh.y = __float2bfloat16(hn1);
            hl.x = __float2bfloat16(hn0 - __bfloat162float(hh.x));
            hl.y = __float2bfloat16(hn1 - __bfloat162float(hh.y));
            int bg2 = b0g + ab2;
            int gofs = bg2 * 512 + j0 + au2;
            *(__nv_bfloat162*)&g_hx_hi[dir][(s + 1) & 1][gofs] = hh;
            *(__nv_bfloat162*)&g_hx_lo[dir][(s + 1) & 1][gofs] = hl;
            size_t ar = ((size_t)bg2 * TT + t) * 1024 + (size_t)dir * 512 + j0 + au2;
            *(__nv_bfloat162*)&g_Acat_hi[ar] = hh;
            *(__nv_bfloat162*)&g_Acat_lo[ar] = hl;
        }
        __syncthreads();
        if (tid == 0) {
            bar_release(bar);
            unsigned tg = 32u * (unsigned)(s + 2);
            while (ld_acq(bar) < tg) {}
        }
        __syncthreads();
    }
}

// ---------------- final layernorm -> d_out ----------------
__global__ void ln_out_kernel(const float* __restrict__ gH,
                              const float* __restrict__ bH,
                              float* __restrict__ out) {
    __shared__ float red[9];
    int r = blockIdx.x;
    const float* row = g_Hout + (size_t)r * HH;
    int c0 = threadIdx.x, c1 = threadIdx.x + 256;
    float v0 = row[c0], v1 = row[c1];
    float mean = block_reduce(v0 + v1, red) * (1.f / HH);
    float d0 = v0 - mean, d1 = v1 - mean;
    float var = block_reduce(d0 * d0 + d1 * d1, red) * (1.f / HH);
    float rstd = rsqrtf(var + 1e-5f);
    out[(size_t)r * HH + c0] = d0 * rstd * gH[c0] + bH[c0];
    out[(size_t)r * HH + c1] = d1 * rstd * gH[c1] + bH[c1];
}

// ---------------- launch ----------------
extern "C" void kernel_launch(void* const* d_in, const int* in_sizes, int n_in,
                              void* d_out, int out_size) {
    const float* x     = (const float*)d_in[0];
    const float* Wih_f = (const float*)d_in[2];
    const float* Whh_f = (const float*)d_in[3];
    const float* bih_f = (const float*)d_in[4];
    const float* bhh_f = (const float*)d_in[5];
    const float* Wih_b = (const float*)d_in[6];
    const float* Whh_b = (const float*)d_in[7];
    const float* bih_b = (const float*)d_in[8];
    const float* bhh_b = (const float*)d_in[9];
    const float* Wg    = (const float*)d_in[10];
    const float* bg    = (const float*)d_in[11];
    const float* gx    = (const float*)d_in[12];
    const float* bx    = (const float*)d_in[13];
    const float* gH    = (const float*)d_in[14];
    const float* bH    = (const float*)d_in[15];
    float* out = (float*)d_out;

    const int scan_smem = (64 * SPAD * 2 + 32 * SPAD * 2) * 2     /* bf16 tiles */
                        + (32 * 66 + 512 + 64) * 4;               /* fp32 */
    cudaFuncSetAttribute(scan_kernel, cudaFuncAttributeMaxDynamicSharedMemorySize, scan_smem);

    ln_x_kernel<<<BB * TT, 256>>>(x, gx, bx);
    convW_proj<<<4096, 256>>>(Wih_f, Wih_b);
    convW_gate<<<512, 256>>>(Wg);
    mm_kernel<512, 0><<<dim3(4096 / 128, (BB * TT) / 128), 256>>>(bih_f, bih_b);
    reset_kernel<<<1, 1>>>();
    scan_kernel<<<128, 256, scan_smem>>>(Whh_f, bhh_f, Whh_b, bhh_b);
    mm_kernel<1024, 1><<<dim3(512 / 128, (BB * TT) / 128), 256>>>(bg, bg);
    ln_out_kernel<<<BB * TT, 256>>>(gH, bH, out);
}

// round 7
// speedup vs baseline: 3.8152x; 1.2921x over previous
#include <cuda_runtime.h>
#include <cuda_bf16.h>
#include <cuda_fp16.h>
#include <math.h>

#define BB   64
#define TT   1024
#define CC   512
#define HH   512
#define G4   2048
#define PADK 40   // padded k-stride for mm_kernel smem tiles (80B rows, 16B-aligned)
#define SPAD 520  // padded k-stride for scan smem tiles (1040B rows)

// ---------------- scratch (static device memory; no allocs) ----------------
__device__ __nv_bfloat16 g_Axn_hi[(size_t)TT * BB * CC];
__device__ __nv_bfloat16 g_Axn_lo[(size_t)TT * BB * CC];
__device__ __nv_bfloat16 g_Bp_hi[4096 * 512];
__device__ __nv_bfloat16 g_Bp_lo[4096 * 512];
__device__ float g_xg_f[(size_t)TT * BB * G4];
__device__ float g_xg_b[(size_t)TT * BB * G4];
__device__ __nv_bfloat16 g_Acat_hi[(size_t)BB * TT * 2 * HH];
__device__ __nv_bfloat16 g_Acat_lo[(size_t)BB * TT * 2 * HH];
__device__ __nv_bfloat16 g_Bg_hi[512 * 1024];
__device__ __nv_bfloat16 g_Bg_lo[512 * 1024];
__device__ __half g_hx[2][2][BB * HH];                     // [dir][parity] fp16 h exchange
__device__ float g_Hout[(size_t)BB * TT * HH];
__device__ unsigned int g_barr[128];                       // counters at 0,32,64,96

// ---------------- fast math ----------------
__device__ __forceinline__ float ex2f(float x) { float r; asm("ex2.approx.f32 %0, %1;" : "=f"(r) : "f"(x)); return r; }
__device__ __forceinline__ float rcpf(float x) { float r; asm("rcp.approx.f32 %0, %1;" : "=f"(r) : "f"(x)); return r; }
__device__ __forceinline__ float fsig(float x) { return rcpf(1.f + ex2f(-1.4426950408889634f * x)); }
__device__ __forceinline__ float ftanh(float x) { return 1.f - 2.f * rcpf(1.f + ex2f(2.8853900817779268f * x)); }

// ---------------- mma helpers ----------------
__device__ __forceinline__ void mma_bf16(float* d, const unsigned* a, const unsigned* b) {
    asm volatile(
        "mma.sync.aligned.m16n8k16.row.col.f32.bf16.bf16.f32 "
        "{%0,%1,%2,%3}, {%4,%5,%6,%7}, {%8,%9}, {%0,%1,%2,%3};"
        : "+f"(d[0]), "+f"(d[1]), "+f"(d[2]), "+f"(d[3])
        : "r"(a[0]), "r"(a[1]), "r"(a[2]), "r"(a[3]), "r"(b[0]), "r"(b[1]));
}
__device__ __forceinline__ void mma_f16(float* d, const unsigned* a, const unsigned* b) {
    asm volatile(
        "mma.sync.aligned.m16n8k16.row.col.f32.f16.f16.f32 "
        "{%0,%1,%2,%3}, {%4,%5,%6,%7}, {%8,%9}, {%0,%1,%2,%3};"
        : "+f"(d[0]), "+f"(d[1]), "+f"(d[2]), "+f"(d[3])
        : "r"(a[0]), "r"(a[1]), "r"(a[2]), "r"(a[3]), "r"(b[0]), "r"(b[1]));
}

#define LDSMX4(R, ADDR) \
    asm volatile("ldmatrix.sync.aligned.m8n8.x4.shared.b16 {%0,%1,%2,%3}, [%4];" \
                 : "=r"((R)[0]), "=r"((R)[1]), "=r"((R)[2]), "=r"((R)[3]) : "r"(ADDR))

#define CPASYNC16(SMEM, GPTR) \
    asm volatile("cp.async.cg.shared.global [%0], [%1], 16;" :: "r"(SMEM), "l"(GPTR))

__device__ __forceinline__ void bar_release(unsigned* p) {
    asm volatile("red.release.gpu.global.add.u32 [%0], 1;" :: "l"(p) : "memory");
}
__device__ __forceinline__ unsigned ld_acq(const unsigned* p) {
    unsigned v;
    asm volatile("ld.acquire.gpu.global.u32 %0, [%1];" : "=r"(v) : "l"(p) : "memory");
    return v;
}
__device__ __forceinline__ unsigned s2u(const void* p) {
    unsigned r;
    asm("{ .reg .u64 t; cvta.to.shared.u64 t, %1; cvt.u32.u64 %0, t; }" : "=r"(r) : "l"(p));
    return r;
}

// ---------------- block reduce ----------------
__device__ __forceinline__ float block_reduce(float v, float* red) {
    int lane = threadIdx.x & 31, wid = threadIdx.x >> 5;
#pragma unroll
    for (int o = 16; o > 0; o >>= 1) v += __shfl_xor_sync(0xffffffffu, v, o);
    if (lane == 0) red[wid] = v;
    __syncthreads();
    if (wid == 0) {
        float w = (lane < 8) ? red[lane] : 0.f;
#pragma unroll
        for (int o = 4; o > 0; o >>= 1) w += __shfl_xor_sync(0xffffffffu, w, o);
        if (lane == 0) red[8] = w;
    }
    __syncthreads();
    float r = red[8];
    __syncthreads();
    return r;
}

// ---------------- kernel 1: layernorm(x) -> bf16 hi/lo (time-major) ----------------
__global__ void ln_x_kernel(const float* __restrict__ x,
                            const float* __restrict__ gx,
                            const float* __restrict__ bx) {
    __shared__ float red[9];
    int r = blockIdx.x;
    int b = r >> 10, t = r & 1023;
    const float* row = x + (size_t)r * CC;
    int c0 = threadIdx.x, c1 = threadIdx.x + 256;
    float v0 = row[c0], v1 = row[c1];
    float mean = block_reduce(v0 + v1, red) * (1.f / CC);
    float d0 = v0 - mean, d1 = v1 - mean;
    float var = block_reduce(d0 * d0 + d1 * d1, red) * (1.f / CC);
    float rstd = rsqrtf(var + 1e-5f);
    size_t base = ((size_t)t * BB + b) * CC;
    float y0 = d0 * rstd * gx[c0] + bx[c0];
    float y1 = d1 * rstd * gx[c1] + bx[c1];
    __nv_bfloat16 h0 = __float2bfloat16(y0);
    __nv_bfloat16 h1 = __float2bfloat16(y1);
    g_Axn_hi[base + c0] = h0;
    g_Axn_hi[base + c1] = h1;
    g_Axn_lo[base + c0] = __float2bfloat16(y0 - __bfloat162float(h0));
    g_Axn_lo[base + c1] = __float2bfloat16(y1 - __bfloat162float(h1));
}

// ---------------- weight conversion kernels ----------------
__global__ void convW_proj(const float* __restrict__ Wf, const float* __restrict__ Wb) {
    int n = blockIdx.x;
    const float* src = (n < 2048) ? (Wf + (size_t)n * 512) : (Wb + (size_t)(n - 2048) * 512);
    size_t base = (size_t)n * 512;
    for (int k = threadIdx.x; k < 512; k += 256) {
        float v = src[k];
        __nv_bfloat16 h = __float2bfloat16(v);
        g_Bp_hi[base + k] = h;
        g_Bp_lo[base + k] = __float2bfloat16(v - __bfloat162float(h));
    }
}

__global__ void convW_gate(const float* __restrict__ Wg) {
    int n = blockIdx.x;
    size_t base = (size_t)n * 1024;
    for (int k = threadIdx.x; k < 1024; k += 256) {
        float v = Wg[base + k];
        __nv_bfloat16 h = __float2bfloat16(v);
        g_Bg_hi[base + k] = h;
        g_Bg_lo[base + k] = __float2bfloat16(v - __bfloat162float(h));
    }
}

// ---------------- HMMA GEMM (bf16 hi/lo, 3 passes, ldmatrix fragments) ----------
template <int KDIM, int EPI>
__global__ void __launch_bounds__(256, 1) mm_kernel(const float* __restrict__ bias0,
                                                    const float* __restrict__ bias1) {
    __shared__ __nv_bfloat16 sAh[128 * PADK];
    __shared__ __nv_bfloat16 sAl[128 * PADK];
    __shared__ __nv_bfloat16 sBh[128 * PADK];
    __shared__ __nv_bfloat16 sBl[128 * PADK];

    const int tid = threadIdx.x;
    const int warp = tid >> 5, lane = tid & 31;
    const int g = lane >> 2, q = lane & 3;
    const int wm = (warp >> 1) * 32;
    const int wn = (warp & 1) * 64;
    const int m0 = blockIdx.y * 128;
    const int n0 = blockIdx.x * 128;

    const __nv_bfloat16* Ahi = (EPI == 0) ? g_Axn_hi : g_Acat_hi;
    const __nv_bfloat16* Alo = (EPI == 0) ? g_Axn_lo : g_Acat_lo;
    const __nv_bfloat16* Bhi = (EPI == 0) ? g_Bp_hi : g_Bg_hi;
    const __nv_bfloat16* Blo = (EPI == 0) ? g_Bp_lo : g_Bg_lo;

    const int r0 = tid >> 2, kq0 = (tid & 3) * 8;
    const int r1 = (tid + 256) >> 2, kq1 = ((tid + 256) & 3) * 8;
    const __nv_bfloat16* pAh0 = Ahi + (size_t)(m0 + r0) * KDIM + kq0;
    const __nv_bfloat16* pAh1 = Ahi + (size_t)(m0 + r1) * KDIM + kq1;
    const __nv_bfloat16* pAl0 = Alo + (size_t)(m0 + r0) * KDIM + kq0;
    const __nv_bfloat16* pAl1 = Alo + (size_t)(m0 + r1) * KDIM + kq1;
    const __nv_bfloat16* pBh0 = Bhi + (size_t)(n0 + r0) * KDIM + kq0;
    const __nv_bfloat16* pBh1 = Bhi + (size_t)(n0 + r1) * KDIM + kq1;
    const __nv_bfloat16* pBl0 = Blo + (size_t)(n0 + r0) * KDIM + kq0;
    const __nv_bfloat16* pBl1 = Blo + (size_t)(n0 + r1) * KDIM + kq1;

    // ldmatrix lane addressing
    const int lrow = (lane & 7) + 8 * ((lane >> 3) & 1);
    const int lcol = 8 * (lane >> 4);
    const unsigned uAh = s2u(sAh), uAl = s2u(sAl), uBh = s2u(sBh), uBl = s2u(sBl);
    const unsigned offA0 = (unsigned)(((wm + lrow) * PADK + lcol) * 2);
    const unsigned offA1 = offA0 + 16 * PADK * 2;
    const unsigned offB  = (unsigned)(((wn + lrow) * PADK + lcol) * 2);

    float acc[2][8][4];
#pragma unroll
    for (int i = 0; i < 2; ++i)
#pragma unroll
        for (int j = 0; j < 8; ++j)
#pragma unroll
            for (int v = 0; v < 4; ++v) acc[i][j][v] = 0.f;

    uint4 vAh0 = *(const uint4*)pAh0, vAh1 = *(const uint4*)pAh1;
    uint4 vAl0 = *(const uint4*)pAl0, vAl1 = *(const uint4*)pAl1;
    uint4 vBh0 = *(const uint4*)pBh0, vBh1 = *(const uint4*)pBh1;
    uint4 vBl0 = *(const uint4*)pBl0, vBl1 = *(const uint4*)pBl1;

    const int NCH = KDIM / 32;
    for (int c = 0; c < NCH; ++c) {
        *(uint4*)&sAh[r0 * PADK + kq0] = vAh0;  *(uint4*)&sAh[r1 * PADK + kq1] = vAh1;
        *(uint4*)&sAl[r0 * PADK + kq0] = vAl0;  *(uint4*)&sAl[r1 * PADK + kq1] = vAl1;
        *(uint4*)&sBh[r0 * PADK + kq0] = vBh0;  *(uint4*)&sBh[r1 * PADK + kq1] = vBh1;
        *(uint4*)&sBl[r0 * PADK + kq0] = vBl0;  *(uint4*)&sBl[r1 * PADK + kq1] = vBl1;
        __syncthreads();

        if (c + 1 < NCH) {
            int koff = (c + 1) * 32;
            vAh0 = *(const uint4*)(pAh0 + koff);  vAh1 = *(const uint4*)(pAh1 + koff);
            vAl0 = *(const uint4*)(pAl0 + koff);  vAl1 = *(const uint4*)(pAl1 + koff);
            vBh0 = *(const uint4*)(pBh0 + koff);  vBh1 = *(const uint4*)(pBh1 + koff);
            vBl0 = *(const uint4*)(pBl0 + koff);  vBl1 = *(const uint4*)(pBl1 + koff);
        }

#pragma unroll
        for (int ks = 0; ks < 32; ks += 16) {
            unsigned ah0[4], ah1[4], al0[4], al1[4];
            LDSMX4(ah0, uAh + offA0 + ks * 2);
            LDSMX4(ah1, uAh + offA1 + ks * 2);
            LDSMX4(al0, uAl + offA0 + ks * 2);
            LDSMX4(al1, uAl + offA1 + ks * 2);
#pragma unroll
            for (int p = 0; p < 4; ++p) {
                unsigned rbh[4], rbl[4];
                LDSMX4(rbh, uBh + offB + (p * 16 * PADK + ks) * 2);
                LDSMX4(rbl, uBl + offB + (p * 16 * PADK + ks) * 2);
#pragma unroll
                for (int e = 0; e < 2; ++e) {
                    unsigned bh2[2] = {rbh[e], rbh[2 + e]};
                    unsigned bl2[2] = {rbl[e], rbl[2 + e]};
                    int nt = 2 * p + e;
                    mma_bf16(acc[0][nt], ah0, bh2);
                    mma_bf16(acc[0][nt], ah0, bl2);
                    mma_bf16(acc[0][nt], al0, bh2);
                    mma_bf16(acc[1][nt], ah1, bh2);
                    mma_bf16(acc[1][nt], ah1, bl2);
                    mma_bf16(acc[1][nt], al1, bh2);
                }
            }
        }
        __syncthreads();
    }

    if (EPI == 0) {
        const bool isf = (n0 < 2048);
        float* Y = isf ? g_xg_f : g_xg_b;
        const float* bias = isf ? bias0 : bias1;
        const int nb = (n0 & 2047) + wn;
#pragma unroll
        for (int mt = 0; mt < 2; ++mt) {
            int mrow = m0 + wm + mt * 16 + g;
#pragma unroll
            for (int nt = 0; nt < 8; ++nt) {
                int ncol = nb + nt * 8 + 2 * q;
                float bx0 = bias[ncol], bx1 = bias[ncol + 1];
                float2 v0 = make_float2(acc[mt][nt][0] + bx0, acc[mt][nt][1] + bx1);
                float2 v1 = make_float2(acc[mt][nt][2] + bx0, acc[mt][nt][3] + bx1);
                *(float2*)(Y + (size_t)mrow * 2048 + ncol) = v0;
                *(float2*)(Y + (size_t)(mrow + 8) * 2048 + ncol) = v1;
            }
        }
    } else {
#pragma unroll
        for (int mt = 0; mt < 2; ++mt) {
            int mrow = m0 + wm + mt * 16 + g;
#pragma unroll
            for (int nt = 0; nt < 8; ++nt) {
                int ncol = n0 + wn + nt * 8 + 2 * q;
                float bx0 = bias0[ncol], bx1 = bias0[ncol + 1];
#pragma unroll
                for (int hh = 0; hh < 2; ++hh) {
                    int m = mrow + hh * 8;
                    float s0 = fsig(acc[mt][nt][2 * hh + 0] + bx0);
                    float s1 = fsig(acc[mt][nt][2 * hh + 1] + bx1);
                    size_t ab = (size_t)m * 1024 + ncol;
                    __nv_bfloat162 fh = *(const __nv_bfloat162*)(g_Acat_hi + ab);
                    __nv_bfloat162 fl = *(const __nv_bfloat162*)(g_Acat_lo + ab);
                    __nv_bfloat162 wh = *(const __nv_bfloat162*)(g_Acat_hi + ab + 512);
                    __nv_bfloat162 wl = *(const __nv_bfloat162*)(g_Acat_lo + ab + 512);
                    float fwx = __bfloat162float(fh.x) + __bfloat162float(fl.x);
                    float fwy = __bfloat162float(fh.y) + __bfloat162float(fl.y);
                    float bwx = __bfloat162float(wh.x) + __bfloat162float(wl.x);
                    float bwy = __bfloat162float(wh.y) + __bfloat162float(wl.y);
                    float2 o;
                    o.x = s0 * fwx + (1.f - s0) * bwx;
                    o.y = s1 * fwy + (1.f - s1) * bwy;
                    *(float2*)(g_Hout + (size_t)m * 512 + ncol) = o;
                }
            }
        }
    }
}

// ---------------- barrier reset ----------------
__global__ void reset_kernel() {
    g_barr[0] = 0u; g_barr[32] = 0u; g_barr[64] = 0u; g_barr[96] = 0u;
}

// ---------------- persistent bidirectional LSTM scan (fp16 single-pass HMMA) -------
// 128 CTAs: dir = bx>>6, grp = (bx>>5)&1 (32 batches), sl = bx&31 -> 16 units (64 cols)
__global__ void __launch_bounds__(256, 1) scan_kernel(
    const float* __restrict__ Whh_f, const float* __restrict__ bhh_f,
    const float* __restrict__ Whh_b, const float* __restrict__ bhh_b) {
    extern __shared__ char smc[];
    __half* sB = (__half*)smc;                 // [64][SPAD] Whh fp16 (static all steps)
    __half* sH = sB + 64 * SPAD;               // [32][SPAD] h staging fp16
    float* sG   = (float*)(sH + 32 * SPAD);    // [32][66]
    float* sC   = sG + 32 * 66;                // [512]
    float* sBhh = sC + 512;                    // [64]

    const int tid  = threadIdx.x;
    const int warp = tid >> 5, lane = tid & 31;
    const int g = lane >> 2, q = lane & 3;
    const int dir = blockIdx.x >> 6;
    const int grp = (blockIdx.x >> 5) & 1;
    const int j0  = (blockIdx.x & 31) * 16;
    const int b0g = grp * 32;
    const int wm  = (warp & 1) * 16;          // m (batch) offset
    const int wn  = (warp >> 1) * 16;         // n (gate col) offset

    const float* Whh = dir ? Whh_b : Whh_f;
    const float* bhh = dir ? bhh_b : bhh_f;
    const float* xg  = dir ? g_xg_b : g_xg_f;
    unsigned* bar = &g_barr[(dir * 2 + grp) * 32];

    const unsigned uB = s2u(sB);
    const unsigned uH = s2u(sH);

    // ---- load Whh slice [64 cols][512] fp16 ----
    {
        int row = tid >> 2;
        int k0 = (tid & 3) * 128;
        int ngl = (row >> 4) * 512 + j0 + (row & 15);
        const float* src = Whh + (size_t)ngl * 512 + k0;
#pragma unroll
        for (int k4 = 0; k4 < 128; k4 += 4) {
            float4 v = *(const float4*)(src + k4);
            sB[row * SPAD + k0 + k4 + 0] = __float2half(v.x);
            sB[row * SPAD + k0 + k4 + 1] = __float2half(v.y);
            sB[row * SPAD + k0 + k4 + 2] = __float2half(v.z);
            sB[row * SPAD + k0 + k4 + 3] = __float2half(v.w);
        }
    }
    if (tid < 64) sBhh[tid] = bhh[(tid >> 4) * 512 + j0 + (tid & 15)];
    for (int idx = tid; idx < 512; idx += 256) sC[idx] = 0.f;
    {
        int i2 = tid * 2;
        int bl2 = i2 >> 4, u = i2 & 15;
        __half2 z2 = __floats2half2_rn(0.f, 0.f);
        *(__half2*)&g_hx[dir][0][(b0g + bl2) * 512 + j0 + u] = z2;
    }
    __syncthreads();
    if (tid == 0) {
        bar_release(bar);
        while (ld_acq(bar) < 32u) {}
    }
    __syncthreads();

    // fragment addressing (static)
    const int lrow = (lane & 7) + 8 * ((lane >> 3) & 1);
    const int lcol = 8 * (lane >> 4);
    const unsigned aA = uH + (unsigned)(((wm + lrow) * SPAD + lcol) * 2);
    const unsigned aB = uB + (unsigned)(((wn + lrow) * SPAD + lcol) * 2);

    // epilogue indices (static)
    const int c0a = wn + 2 * q;
    const int c0b = wn + 8 + 2 * q;
    const int ngba = (c0a >> 4) * 512 + j0 + (c0a & 15);
    const int ngbb = (c0b >> 4) * 512 + j0 + (c0b & 15);
    const int r0 = wm + g, r1 = r0 + 8;
    const float2 bb0 = *(const float2*)&sBhh[c0a];
    const float2 bb1 = *(const float2*)&sBhh[c0b];

    const int ab2 = (tid * 2) >> 4, au2 = (tid * 2) & 15;

    for (int s = 0; s < TT; ++s) {
        const int t = dir ? (TT - 1 - s) : s;

        // ---- xg prefetch (DRAM, consumed in epilogue) ----
        const float* xgt = xg + (size_t)t * BB * G4;
        float2 xv00 = __ldcg((const float2*)(xgt + (size_t)(b0g + r0) * G4 + ngba));
        float2 xv01 = __ldcg((const float2*)(xgt + (size_t)(b0g + r1) * G4 + ngba));
        float2 xv10 = __ldcg((const float2*)(xgt + (size_t)(b0g + r0) * G4 + ngbb));
        float2 xv11 = __ldcg((const float2*)(xgt + (size_t)(b0g + r1) * G4 + ngbb));

        // ---- stage h[32,512] fp16 in two K-halves (pipelined cp.async) ----
        const char* hg = (const char*)&g_hx[dir][s & 1][b0g * 512];
#pragma unroll
        for (int ha = 0; ha < 2; ++ha) {
#pragma unroll
            for (int i = 0; i < 2; ++i) {
                int idx = tid + i * 256;               // 0..511 (16B chunks in half)
                int row = idx >> 4;                    // 0..31
                int c8 = (idx & 15) * 16 + ha * 256;   // 16 fp16 per... (2 chunks)
                // copy 2 chunks of 8 fp16 each => use 8-elem chunks:
                // (idx&15)*16 would skip; handle as 8-elem chunks below.
                (void)row; (void)c8;
            }
            // 32 rows x 256 fp16 per half = 512B/row = 32 chunks/row => 1024 chunks
#pragma unroll
            for (int i = 0; i < 4; ++i) {
                int idx = tid + i * 256;               // 0..1023
                int row = idx >> 5;                    // 0..31
                int c8 = (idx & 31) * 8 + ha * 256;    // fp16 elem offset
                unsigned so = (unsigned)((row * SPAD + c8) * 2);
                int go = (row * 512 + c8) * 2;
                CPASYNC16(uH + so, hg + go);
            }
            asm volatile("cp.async.commit_group;");
        }
        asm volatile("cp.async.wait_group 1;" ::: "memory");
        __syncthreads();

        float acc[2][4];
#pragma unroll
        for (int nt = 0; nt < 2; ++nt)
#pragma unroll
            for (int v = 0; v < 4; ++v) acc[nt][v] = 0.f;

#pragma unroll
        for (int ks = 0; ks < 256; ks += 16) {
            unsigned a4[4], b4[4];
            LDSMX4(a4, aA + (unsigned)(ks * 2));
            LDSMX4(b4, aB + (unsigned)(ks * 2));
#pragma unroll
            for (int e = 0; e < 2; ++e) {
                unsigned b2[2] = {b4[e], b4[2 + e]};
                mma_f16(acc[e], a4, b2);
            }
        }
        asm volatile("cp.async.wait_group 0;" ::: "memory");
        __syncthreads();
#pragma unroll
        for (int ks = 256; ks < 512; ks += 16) {
            unsigned a4[4], b4[4];
            LDSMX4(a4, aA + (unsigned)(ks * 2));
            LDSMX4(b4, aB + (unsigned)(ks * 2));
#pragma unroll
            for (int e = 0; e < 2; ++e) {
                unsigned b2[2] = {b4[e], b4[2 + e]};
                mma_f16(acc[e], a4, b2);
            }
        }

        // ---- epilogue: add xg + bhh, write gates to smem ----
        *(float2*)&sG[r0 * 66 + c0a] =
            make_float2(acc[0][0] + xv00.x + bb0.x, acc[0][1] + xv00.y + bb0.y);
        *(float2*)&sG[r1 * 66 + c0a] =
            make_float2(acc[0][2] + xv01.x + bb0.x, acc[0][3] + xv01.y + bb0.y);
        *(float2*)&sG[r0 * 66 + c0b] =
            make_float2(acc[1][0] + xv10.x + bb1.x, acc[1][1] + xv10.y + bb1.y);
        *(float2*)&sG[r1 * 66 + c0b] =
            make_float2(acc[1][2] + xv11.x + bb1.x, acc[1][3] + xv11.y + bb1.y);
        __syncthreads();

        // ---- activation + h production ----
        {
            float2 gi = *(const float2*)&sG[ab2 * 66 + au2];
            float2 gf = *(const float2*)&sG[ab2 * 66 + 16 + au2];
            float2 gg = *(const float2*)&sG[ab2 * 66 + 32 + au2];
            float2 go = *(const float2*)&sG[ab2 * 66 + 48 + au2];
            float2 cold = *(const float2*)&sC[tid * 2];
            float cn0 = fsig(gf.x) * cold.x + fsig(gi.x) * ftanh(gg.x);
            float cn1 = fsig(gf.y) * cold.y + fsig(gi.y) * ftanh(gg.y);
            float hn0 = fsig(go.x) * ftanh(cn0);
            float hn1 = fsig(go.y) * ftanh(cn1);
            *(float2*)&sC[tid * 2] = make_float2(cn0, cn1);
            int bg2 = b0g + ab2;
            int gofs = bg2 * 512 + j0 + au2;
            *(__half2*)&g_hx[dir][(s + 1) & 1][gofs] = __floats2half2_rn(hn0, hn1);
            __nv_bfloat162 hh, hl;
            hh.x = __float2bfloat16(hn0);
            hh.y = __float2bfloat16(hn1);
            hl.x = __float2bfloat16(hn0 - __bfloat162float(hh.x));
            hl.y = __float2bfloat16(hn1 - __bfloat162float(hh.y));
            size_t ar = ((size_t)bg2 * TT + t) * 1024 + (size_t)dir * 512 + j0 + au2;
            *(__nv_bfloat162*)&g_Acat_hi[ar] = hh;
            *(__nv_bfloat162*)&g_Acat_lo[ar] = hl;
        }
        __syncthreads();
        if (tid == 0) {
            bar_release(bar);
            unsigned tg = 32u * (unsigned)(s + 2);
            while (ld_acq(bar) < tg) {}
        }
        __syncthreads();
    }
}

// ---------------- final layernorm -> d_out ----------------
__global__ void ln_out_kernel(const float* __restrict__ gH,
                              const float* __restrict__ bH,
                              float* __restrict__ out) {
    __shared__ float red[9];
    int r = blockIdx.x;
    const float* row = g_Hout + (size_t)r * HH;
    int c0 = threadIdx.x, c1 = threadIdx.x + 256;
    float v0 = row[c0], v1 = row[c1];
    float mean = block_reduce(v0 + v1, red) * (1.f / HH);
    float d0 = v0 - mean, d1 = v1 - mean;
    float var = block_reduce(d0 * d0 + d1 * d1, red) * (1.f / HH);
    float rstd = rsqrtf(var + 1e-5f);
    out[(size_t)r * HH + c0] = d0 * rstd * gH[c0] + bH[c0];
    out[(size_t)r * HH + c1] = d1 * rstd * gH[c1] + bH[c1];
}

// ---------------- launch ----------------
extern "C" void kernel_launch(void* const* d_in, const int* in_sizes, int n_in,
                              void* d_out, int out_size) {
    const float* x     = (const float*)d_in[0];
    const float* Wih_f = (const float*)d_in[2];
    const float* Whh_f = (const float*)d_in[3];
    const float* bih_f = (const float*)d_in[4];
    const float* bhh_f = (const float*)d_in[5];
    const float* Wih_b = (const float*)d_in[6];
    const float* Whh_b = (const float*)d_in[7];
    const float* bih_b = (const float*)d_in[8];
    const float* bhh_b = (const float*)d_in[9];
    const float* Wg    = (const float*)d_in[10];
    const float* bg    = (const float*)d_in[11];
    const float* gx    = (const float*)d_in[12];
    const float* bx    = (const float*)d_in[13];
    const float* gH    = (const float*)d_in[14];
    const float* bH    = (const float*)d_in[15];
    float* out = (float*)d_out;

    const int scan_smem = (64 * SPAD + 32 * SPAD) * 2        /* fp16 tiles */
                        + (32 * 66 + 512 + 64) * 4;          /* fp32 */
    cudaFuncSetAttribute(scan_kernel, cudaFuncAttributeMaxDynamicSharedMemorySize, scan_smem);

    ln_x_kernel<<<BB * TT, 256>>>(x, gx, bx);
    convW_proj<<<4096, 256>>>(Wih_f, Wih_b);
    convW_gate<<<512, 256>>>(Wg);
    mm_kernel<512, 0><<<dim3(4096 / 128, (BB * TT) / 128), 256>>>(bih_f, bih_b);
    reset_kernel<<<1, 1>>>();
    scan_kernel<<<128, 256, scan_smem>>>(Whh_f, bhh_f, Whh_b, bhh_b);
    mm_kernel<1024, 1><<<dim3(512 / 128, (BB * TT) / 128), 256>>>(bg, bg);
    ln_out_kernel<<<BB * TT, 256>>>(gH, bH, out);
}

// round 8
// speedup vs baseline: 5.7755x; 1.5138x over previous
#include <cuda_runtime.h>
#include <cuda_bf16.h>
#include <cuda_fp16.h>
#include <math.h>

#define BB   64
#define TT   1024
#define CC   512
#define HH   512
#define G4   2048
#define PADK 40   // padded k-stride for mm_kernel smem tiles
#define SPAD 520  // padded k-stride for scan smem tiles

// ---------------- scratch (static device memory; no allocs) ----------------
__device__ __half g_Axn[(size_t)TT * BB * CC];         // LN(x) fp16, time-major [t*B+b][C]
__device__ __half g_Bp[4096 * 512];                    // stacked Wih_f | Wih_b fp16
__device__ float g_xg_f[(size_t)TT * BB * G4];         // input projection fwd (fp32)
__device__ float g_xg_b[(size_t)TT * BB * G4];
__device__ __half g_AcatH[(size_t)BB * TT * 2 * HH];   // concat(fw,bw) fp16 [b*T+t][2H]
__device__ __half g_Bg[512 * 1024];                    // Wg fp16
__device__ __half g_hx[2][2][BB * HH];                 // [dir][parity] fp16 h exchange
__device__ float g_Hout[(size_t)BB * TT * HH];
__device__ unsigned int g_barr[256];                   // 8 counters at i*32

// ---------------- fast math ----------------
__device__ __forceinline__ float ex2f(float x) { float r; asm("ex2.approx.f32 %0, %1;" : "=f"(r) : "f"(x)); return r; }
__device__ __forceinline__ float rcpf(float x) { float r; asm("rcp.approx.f32 %0, %1;" : "=f"(r) : "f"(x)); return r; }
__device__ __forceinline__ float fsig(float x) { return rcpf(1.f + ex2f(-1.4426950408889634f * x)); }
__device__ __forceinline__ float ftanh(float x) { return 1.f - 2.f * rcpf(1.f + ex2f(2.8853900817779268f * x)); }

// ---------------- mma helper ----------------
__device__ __forceinline__ void mma_f16(float* d, const unsigned* a, const unsigned* b) {
    asm volatile(
        "mma.sync.aligned.m16n8k16.row.col.f32.f16.f16.f32 "
        "{%0,%1,%2,%3}, {%4,%5,%6,%7}, {%8,%9}, {%0,%1,%2,%3};"
        : "+f"(d[0]), "+f"(d[1]), "+f"(d[2]), "+f"(d[3])
        : "r"(a[0]), "r"(a[1]), "r"(a[2]), "r"(a[3]), "r"(b[0]), "r"(b[1]));
}

#define LDSMX4(R, ADDR) \
    asm volatile("ldmatrix.sync.aligned.m8n8.x4.shared.b16 {%0,%1,%2,%3}, [%4];" \
                 : "=r"((R)[0]), "=r"((R)[1]), "=r"((R)[2]), "=r"((R)[3]) : "r"(ADDR))

#define CPASYNC16(SMEM, GPTR) \
    asm volatile("cp.async.cg.shared.global [%0], [%1], 16;" :: "r"(SMEM), "l"(GPTR))

__device__ __forceinline__ void bar_release(unsigned* p) {
    asm volatile("red.release.gpu.global.add.u32 [%0], 1;" :: "l"(p) : "memory");
}
__device__ __forceinline__ unsigned ld_acq(const unsigned* p) {
    unsigned v;
    asm volatile("ld.acquire.gpu.global.u32 %0, [%1];" : "=r"(v) : "l"(p) : "memory");
    return v;
}
__device__ __forceinline__ unsigned s2u(const void* p) {
    unsigned r;
    asm("{ .reg .u64 t; cvta.to.shared.u64 t, %1; cvt.u32.u64 %0, t; }" : "=r"(r) : "l"(p));
    return r;
}

// ---------------- block reduce ----------------
__device__ __forceinline__ float block_reduce(float v, float* red) {
    int lane = threadIdx.x & 31, wid = threadIdx.x >> 5;
#pragma unroll
    for (int o = 16; o > 0; o >>= 1) v += __shfl_xor_sync(0xffffffffu, v, o);
    if (lane == 0) red[wid] = v;
    __syncthreads();
    if (wid == 0) {
        float w = (lane < 8) ? red[lane] : 0.f;
#pragma unroll
        for (int o = 4; o > 0; o >>= 1) w += __shfl_xor_sync(0xffffffffu, w, o);
        if (lane == 0) red[8] = w;
    }
    __syncthreads();
    float r = red[8];
    __syncthreads();
    return r;
}

// ---------------- kernel 1: layernorm(x) -> fp16 (time-major) ----------------
__global__ void ln_x_kernel(const float* __restrict__ x,
                            const float* __restrict__ gx,
                            const float* __restrict__ bx) {
    __shared__ float red[9];
    int r = blockIdx.x;
    int b = r >> 10, t = r & 1023;
    const float* row = x + (size_t)r * CC;
    int c0 = threadIdx.x, c1 = threadIdx.x + 256;
    float v0 = row[c0], v1 = row[c1];
    float mean = block_reduce(v0 + v1, red) * (1.f / CC);
    float d0 = v0 - mean, d1 = v1 - mean;
    float var = block_reduce(d0 * d0 + d1 * d1, red) * (1.f / CC);
    float rstd = rsqrtf(var + 1e-5f);
    size_t base = ((size_t)t * BB + b) * CC;
    g_Axn[base + c0] = __float2half(d0 * rstd * gx[c0] + bx[c0]);
    g_Axn[base + c1] = __float2half(d1 * rstd * gx[c1] + bx[c1]);
}

// ---------------- weight conversion ----------------
__global__ void convW_proj(const float* __restrict__ Wf, const float* __restrict__ Wb) {
    int n = blockIdx.x;
    const float* src = (n < 2048) ? (Wf + (size_t)n * 512) : (Wb + (size_t)(n - 2048) * 512);
    size_t base = (size_t)n * 512;
    for (int k = threadIdx.x; k < 512; k += 256) g_Bp[base + k] = __float2half(src[k]);
}
__global__ void convW_gate(const float* __restrict__ Wg) {
    int n = blockIdx.x;
    size_t base = (size_t)n * 1024;
    for (int k = threadIdx.x; k < 1024; k += 256) g_Bg[base + k] = __float2half(Wg[base + k]);
}

// ---------------- HMMA GEMM fp16 single-pass: D = A . B^T ----------
// EPI 0: proj epilogue (bias -> g_xg_f/g_xg_b). EPI 1: gate fusion -> g_Hout.
template <int KDIM, int EPI>
__global__ void __launch_bounds__(256, 1) mm_kernel(const float* __restrict__ bias0,
                                                    const float* __restrict__ bias1) {
    __shared__ __half sA[128 * PADK];
    __shared__ __half sB[128 * PADK];

    const int tid = threadIdx.x;
    const int warp = tid >> 5, lane = tid & 31;
    const int g = lane >> 2, q = lane & 3;
    const int wm = (warp >> 1) * 32;
    const int wn = (warp & 1) * 64;
    const int m0 = blockIdx.y * 128;
    const int n0 = blockIdx.x * 128;

    const __half* A = (EPI == 0) ? g_Axn : g_AcatH;
    const __half* B = (EPI == 0) ? g_Bp : g_Bg;

    const int r0 = tid >> 2, kq0 = (tid & 3) * 8;
    const int r1 = r0 + 64;
    const __half* pA0 = A + (size_t)(m0 + r0) * KDIM + kq0;
    const __half* pA1 = A + (size_t)(m0 + r1) * KDIM + kq0;
    const __half* pB0 = B + (size_t)(n0 + r0) * KDIM + kq0;
    const __half* pB1 = B + (size_t)(n0 + r1) * KDIM + kq0;

    const int lrow = (lane & 7) + 8 * ((lane >> 3) & 1);
    const int lcol = 8 * (lane >> 4);
    const unsigned uA = s2u(sA), uB = s2u(sB);
    const unsigned offA0 = (unsigned)(((wm + lrow) * PADK + lcol) * 2);
    const unsigned offA1 = offA0 + 16 * PADK * 2;
    const unsigned offB  = (unsigned)(((wn + lrow) * PADK + lcol) * 2);

    float acc[2][8][4];
#pragma unroll
    for (int i = 0; i < 2; ++i)
#pragma unroll
        for (int j = 0; j < 8; ++j)
#pragma unroll
            for (int v = 0; v < 4; ++v) acc[i][j][v] = 0.f;

    uint4 vA0 = *(const uint4*)pA0, vA1 = *(const uint4*)pA1;
    uint4 vB0 = *(const uint4*)pB0, vB1 = *(const uint4*)pB1;

    const int NCH = KDIM / 32;
    for (int c = 0; c < NCH; ++c) {
        *(uint4*)&sA[r0 * PADK + kq0] = vA0;  *(uint4*)&sA[r1 * PADK + kq0] = vA1;
        *(uint4*)&sB[r0 * PADK + kq0] = vB0;  *(uint4*)&sB[r1 * PADK + kq0] = vB1;
        __syncthreads();

        if (c + 1 < NCH) {
            int koff = (c + 1) * 32;
            vA0 = *(const uint4*)(pA0 + koff);  vA1 = *(const uint4*)(pA1 + koff);
            vB0 = *(const uint4*)(pB0 + koff);  vB1 = *(const uint4*)(pB1 + koff);
        }

#pragma unroll
        for (int ks = 0; ks < 32; ks += 16) {
            unsigned a0[4], a1[4];
            LDSMX4(a0, uA + offA0 + ks * 2);
            LDSMX4(a1, uA + offA1 + ks * 2);
#pragma unroll
            for (int p = 0; p < 4; ++p) {
                unsigned b4[4];
                LDSMX4(b4, uB + offB + (p * 16 * PADK + ks) * 2);
#pragma unroll
                for (int e = 0; e < 2; ++e) {
                    unsigned b2[2] = {b4[e], b4[2 + e]};
                    int nt = 2 * p + e;
                    mma_f16(acc[0][nt], a0, b2);
                    mma_f16(acc[1][nt], a1, b2);
                }
            }
        }
        __syncthreads();
    }

    if (EPI == 0) {
        const bool isf = (n0 < 2048);
        float* Y = isf ? g_xg_f : g_xg_b;
        const float* bias = isf ? bias0 : bias1;
        const int nb = (n0 & 2047) + wn;
#pragma unroll
        for (int mt = 0; mt < 2; ++mt) {
            int mrow = m0 + wm + mt * 16 + g;
#pragma unroll
            for (int nt = 0; nt < 8; ++nt) {
                int ncol = nb + nt * 8 + 2 * q;
                float bx0 = bias[ncol], bx1 = bias[ncol + 1];
                float2 v0 = make_float2(acc[mt][nt][0] + bx0, acc[mt][nt][1] + bx1);
                float2 v1 = make_float2(acc[mt][nt][2] + bx0, acc[mt][nt][3] + bx1);
                *(float2*)(Y + (size_t)mrow * 2048 + ncol) = v0;
                *(float2*)(Y + (size_t)(mrow + 8) * 2048 + ncol) = v1;
            }
        }
    } else {
#pragma unroll
        for (int mt = 0; mt < 2; ++mt) {
            int mrow = m0 + wm + mt * 16 + g;
#pragma unroll
            for (int nt = 0; nt < 8; ++nt) {
                int ncol = n0 + wn + nt * 8 + 2 * q;
                float bx0 = bias0[ncol], bx1 = bias0[ncol + 1];
#pragma unroll
                for (int hh = 0; hh < 2; ++hh) {
                    int m = mrow + hh * 8;
                    float s0 = fsig(acc[mt][nt][2 * hh + 0] + bx0);
                    float s1 = fsig(acc[mt][nt][2 * hh + 1] + bx1);
                    size_t ab = (size_t)m * 1024 + ncol;
                    float2 fw = __half22float2(*(const __half2*)(g_AcatH + ab));
                    float2 bw = __half22float2(*(const __half2*)(g_AcatH + ab + 512));
                    float2 o;
                    o.x = s0 * fw.x + (1.f - s0) * bw.x;
                    o.y = s1 * fw.y + (1.f - s1) * bw.y;
                    *(float2*)(g_Hout + (size_t)m * 512 + ncol) = o;
                }
            }
        }
    }
}

// ---------------- barrier reset ----------------
__global__ void reset_kernel() {
#pragma unroll
    for (int i = 0; i < 8; ++i) g_barr[i * 32] = 0u;
}

// ---------------- persistent bidirectional LSTM scan (fp16 HMMA, 4-way batch split) ----
// 128 CTAs: dir = bx>>6, grp = (bx>>4)&3 (16 batches), sl = bx&15 -> 32 units (128 cols).
// Each CTA: gates[16,128] = h[16,512] . Whh_slice[128,512]^T (+xg+bhh).
// Syncs with the 15 other CTAs of its (dir,grp).
__global__ void __launch_bounds__(256, 1) scan_kernel(
    const float* __restrict__ Whh_f, const float* __restrict__ bhh_f,
    const float* __restrict__ Whh_b, const float* __restrict__ bhh_b) {
    extern __shared__ char smc[];
    __half* sB = (__half*)smc;                 // [128][SPAD] Whh fp16 (static)
    __half* sH = sB + 128 * SPAD;              // [16][SPAD] h staging
    float* sG   = (float*)(sH + 16 * SPAD);    // [16][130]
    float* sC   = sG + 16 * 130;               // [512] cell (16 b x 32 u)
    float* sBhh = sC + 512;                    // [128]

    const int tid  = threadIdx.x;
    const int warp = tid >> 5, lane = tid & 31;
    const int g = lane >> 2, q = lane & 3;
    const int dir = blockIdx.x >> 6;
    const int grp = (blockIdx.x >> 4) & 3;
    const int j0  = (blockIdx.x & 15) * 32;    // 32 units
    const int b0g = grp * 16;                  // batch offset
    const int wn  = warp * 16;                 // gate-col offset (8 warps x 16 = 128)

    const float* Whh = dir ? Whh_b : Whh_f;
    const float* bhh = dir ? bhh_b : bhh_f;
    const float* xg  = dir ? g_xg_b : g_xg_f;
    unsigned* bar = &g_barr[(dir * 4 + grp) * 32];

    const unsigned uB = s2u(sB);
    const unsigned uH = s2u(sH);

    // ---- load Whh slice [128 cols][512] fp16 ----
    {
        int row = tid >> 1;                    // 0..127
        int k0 = (tid & 1) * 256;
        int ngl = (row >> 5) * 512 + j0 + (row & 31);
        const float* src = Whh + (size_t)ngl * 512 + k0;
#pragma unroll
        for (int k4 = 0; k4 < 256; k4 += 4) {
            float4 v = *(const float4*)(src + k4);
            sB[row * SPAD + k0 + k4 + 0] = __float2half(v.x);
            sB[row * SPAD + k0 + k4 + 1] = __float2half(v.y);
            sB[row * SPAD + k0 + k4 + 2] = __float2half(v.z);
            sB[row * SPAD + k0 + k4 + 3] = __float2half(v.w);
        }
    }
    if (tid < 128) sBhh[tid] = bhh[(tid >> 5) * 512 + j0 + (tid & 31)];
    for (int idx = tid; idx < 512; idx += 256) sC[idx] = 0.f;
    {
        int i2 = tid * 2;                      // 0..510
        int b = i2 >> 5, u = i2 & 31;
        *(__half2*)&g_hx[dir][0][(b0g + b) * 512 + j0 + u] = __floats2half2_rn(0.f, 0.f);
    }
    __syncthreads();
    if (tid == 0) {
        bar_release(bar);
        while (ld_acq(bar) < 16u) {}
    }
    __syncthreads();

    // fragment addressing (static)
    const int lrow = (lane & 7) + 8 * ((lane >> 3) & 1);
    const int lcol = 8 * (lane >> 4);
    const unsigned aA = uH + (unsigned)((lrow * SPAD + lcol) * 2);             // A rows 0..15
    const unsigned aB = uB + (unsigned)(((wn + lrow) * SPAD + lcol) * 2);

    // epilogue indices (static)
    const int c0a = wn + 2 * q;
    const int c0b = wn + 8 + 2 * q;
    const int ngba = (c0a >> 5) * 512 + j0 + (c0a & 31);
    const int ngbb = (c0b >> 5) * 512 + j0 + (c0b & 31);
    const int r0 = g, r1 = g + 8;              // local batch rows
    const float2 bb0 = *(const float2*)&sBhh[c0a];
    const float2 bb1 = *(const float2*)&sBhh[c0b];

    const int ab2 = (tid * 2) >> 5, au2 = (tid * 2) & 31;

    for (int s = 0; s < TT; ++s) {
        const int t = dir ? (TT - 1 - s) : s;

        // ---- xg prefetch (DRAM; consumed in epilogue) ----
        const float* xgt = xg + (size_t)t * BB * G4;
        float2 xv00 = __ldcg((const float2*)(xgt + (size_t)(b0g + r0) * G4 + ngba));
        float2 xv01 = __ldcg((const float2*)(xgt + (size_t)(b0g + r1) * G4 + ngba));
        float2 xv10 = __ldcg((const float2*)(xgt + (size_t)(b0g + r0) * G4 + ngbb));
        float2 xv11 = __ldcg((const float2*)(xgt + (size_t)(b0g + r1) * G4 + ngbb));

        // ---- stage h[16,512] fp16 in two K-halves (pipelined cp.async) ----
        const char* hg = (const char*)&g_hx[dir][s & 1][b0g * 512];
#pragma unroll
        for (int ha = 0; ha < 2; ++ha) {
#pragma unroll
            for (int i = 0; i < 2; ++i) {
                int idx = tid + i * 256;               // 0..511
                int row = idx >> 5;                    // 0..15
                int c8 = (idx & 31) * 8 + ha * 256;
                unsigned so = (unsigned)((row * SPAD + c8) * 2);
                int go = (row * 512 + c8) * 2;
                CPASYNC16(uH + so, hg + go);
            }
            asm volatile("cp.async.commit_group;");
        }
        asm volatile("cp.async.wait_group 1;" ::: "memory");
        __syncthreads();

        float acc[2][4];
#pragma unroll
        for (int nt = 0; nt < 2; ++nt)
#pragma unroll
            for (int v = 0; v < 4; ++v) acc[nt][v] = 0.f;

#pragma unroll
        for (int ks = 0; ks < 256; ks += 16) {
            unsigned a4[4], b4[4];
            LDSMX4(a4, aA + (unsigned)(ks * 2));
            LDSMX4(b4, aB + (unsigned)(ks * 2));
#pragma unroll
            for (int e = 0; e < 2; ++e) {
                unsigned b2[2] = {b4[e], b4[2 + e]};
                mma_f16(acc[e], a4, b2);
            }
        }
        asm volatile("cp.async.wait_group 0;" ::: "memory");
        __syncthreads();
#pragma unroll
        for (int ks = 256; ks < 512; ks += 16) {
            unsigned a4[4], b4[4];
            LDSMX4(a4, aA + (unsigned)(ks * 2));
            LDSMX4(b4, aB + (unsigned)(ks * 2));
#pragma unroll
            for (int e = 0; e < 2; ++e) {
                unsigned b2[2] = {b4[e], b4[2 + e]};
                mma_f16(acc[e], a4, b2);
            }
        }

        // ---- epilogue: add xg + bhh, write gates to smem ----
        *(float2*)&sG[r0 * 130 + c0a] =
            make_float2(acc[0][0] + xv00.x + bb0.x, acc[0][1] + xv00.y + bb0.y);
        *(float2*)&sG[r1 * 130 + c0a] =
            make_float2(acc[0][2] + xv01.x + bb0.x, acc[0][3] + xv01.y + bb0.y);
        *(float2*)&sG[r0 * 130 + c0b] =
            make_float2(acc[1][0] + xv10.x + bb1.x, acc[1][1] + xv10.y + bb1.y);
        *(float2*)&sG[r1 * 130 + c0b] =
            make_float2(acc[1][2] + xv11.x + bb1.x, acc[1][3] + xv11.y + bb1.y);
        __syncthreads();

        // ---- activation + h production (2 consecutive states per thread) ----
        {
            float2 gi = *(const float2*)&sG[ab2 * 130 + au2];
            float2 gf = *(const float2*)&sG[ab2 * 130 + 32 + au2];
            float2 gg = *(const float2*)&sG[ab2 * 130 + 64 + au2];
            float2 go = *(const float2*)&sG[ab2 * 130 + 96 + au2];
            float2 cold = *(const float2*)&sC[tid * 2];
            float cn0 = fsig(gf.x) * cold.x + fsig(gi.x) * ftanh(gg.x);
            float cn1 = fsig(gf.y) * cold.y + fsig(gi.y) * ftanh(gg.y);
            float hn0 = fsig(go.x) * ftanh(cn0);
            float hn1 = fsig(go.y) * ftanh(cn1);
            *(float2*)&sC[tid * 2] = make_float2(cn0, cn1);
            __half2 h2 = __floats2half2_rn(hn0, hn1);
            int bg2 = b0g + ab2;
            *(__half2*)&g_hx[dir][(s + 1) & 1][bg2 * 512 + j0 + au2] = h2;
            size_t ar = ((size_t)bg2 * TT + t) * 1024 + (size_t)dir * 512 + j0 + au2;
            *(__half2*)&g_AcatH[ar] = h2;
        }
        __syncthreads();
        if (tid == 0) {
            bar_release(bar);
            unsigned tg = 16u * (unsigned)(s + 2);
            while (ld_acq(bar) < tg) {}
        }
        __syncthreads();
    }
}

// ---------------- final layernorm -> d_out ----------------
__global__ void ln_out_kernel(const float* __restrict__ gH,
                              const float* __restrict__ bH,
                              float* __restrict__ out) {
    __shared__ float red[9];
    int r = blockIdx.x;
    const float* row = g_Hout + (size_t)r * HH;
    int c0 = threadIdx.x, c1 = threadIdx.x + 256;
    float v0 = row[c0], v1 = row[c1];
    float mean = block_reduce(v0 + v1, red) * (1.f / HH);
    float d0 = v0 - mean, d1 = v1 - mean;
    float var = block_reduce(d0 * d0 + d1 * d1, red) * (1.f / HH);
    float rstd = rsqrtf(var + 1e-5f);
    out[(size_t)r * HH + c0] = d0 * rstd * gH[c0] + bH[c0];
    out[(size_t)r * HH + c1] = d1 * rstd * gH[c1] + bH[c1];
}

// ---------------- launch ----------------
extern "C" void kernel_launch(void* const* d_in, const int* in_sizes, int n_in,
                              void* d_out, int out_size) {
    const float* x     = (const float*)d_in[0];
    const float* Wih_f = (const float*)d_in[2];
    const float* Whh_f = (const float*)d_in[3];
    const float* bih_f = (const float*)d_in[4];
    const float* bhh_f = (const float*)d_in[5];
    const float* Wih_b = (const float*)d_in[6];
    const float* Whh_b = (const float*)d_in[7];
    const float* bih_b = (const float*)d_in[8];
    const float* bhh_b = (const float*)d_in[9];
    const float* Wg    = (const float*)d_in[10];
    const float* bg    = (const float*)d_in[11];
    const float* gx    = (const float*)d_in[12];
    const float* bx    = (const float*)d_in[13];
    const float* gH    = (const float*)d_in[14];
    const float* bH    = (const float*)d_in[15];
    float* out = (float*)d_out;

    const int scan_smem = (128 * SPAD + 16 * SPAD) * 2       /* fp16 tiles */
                        + (16 * 130 + 512 + 128) * 4;        /* fp32 */
    cudaFuncSetAttribute(scan_kernel, cudaFuncAttributeMaxDynamicSharedMemorySize, scan_smem);

    ln_x_kernel<<<BB * TT, 256>>>(x, gx, bx);
    convW_proj<<<4096, 256>>>(Wih_f, Wih_b);
    convW_gate<<<512, 256>>>(Wg);
    mm_kernel<512, 0><<<dim3(4096 / 128, (BB * TT) / 128), 256>>>(bih_f, bih_b);
    reset_kernel<<<1, 1>>>();
    scan_kernel<<<128, 256, scan_smem>>>(Whh_f, bhh_f, Whh_b, bhh_b);
    mm_kernel<1024, 1><<<dim3(512 / 128, (BB * TT) / 128), 256>>>(bg, bg);
    ln_out_kernel<<<BB * TT, 256>>>(gH, bH, out);
}